// round 14
// baseline (speedup 1.0000x reference)
#include <cuda_runtime.h>
#include <cuda_bf16.h>
#include <cuda_fp16.h>
#include <math.h>
#include <stdint.h>

// ---------------- problem constants ----------------
#define B_   2
#define NQ_  8192
#define DM_  256
#define NH_  6
#define DH_  64
#define NL_  3
#define NP_  9
#define NHD_ (NH_*DH_)            // 384
#define NOFF_ (NH_*NL_*NP_*2)     // 324
#define NATT_ (NH_*NL_*NP_)       // 162
#define NOA_  (NOFF_ + NATT_)     // 486
#define TOTHW_ 10080              // 7680+1920+480

// level tables
__device__ __constant__ int   c_W[3]   = {160, 80, 40};
__device__ __constant__ int   c_H[3]   = {48, 24, 12};
__device__ __constant__ int   c_OFF[3] = {0, 7680, 9600};
__device__ __constant__ float c_SX[3]  = {160.f/1280.f, 80.f/1280.f, 40.f/1280.f};
__device__ __constant__ float c_SY[3]  = {48.f/384.f, 24.f/384.f, 12.f/384.f};

// ---------------- scratch (no allocs allowed) ----------------
__device__ __half g_vh16[(size_t)B_ * TOTHW_ * NHD_];   // value projection (fp16)
__device__ float g_oa  [(size_t)B_ * NQ_ * NOA_];       // offsets(324) | attn(162)
__device__ float g_boa [NOA_];

// single fp16 A-planes
__device__ __half g_q16 [(size_t)B_ * NQ_ * DM_];
__device__ __half g_f16 [(size_t)B_ * TOTHW_ * DM_];
__device__ __half g_mid16[(size_t)B_ * NQ_ * NHD_];

// weights transposed [N][K] fp16: Wv(384x256) | Woa(486x256) | Wout(256x384)
#define WV_OFF   0
#define WOA_OFF  (384*256)
#define WOUT_OFF (WOA_OFF + NOA_*256)
#define WTOT_    (WOUT_OFF + 256*384)
__device__ __half g_wh[WTOT_];

// ================= prep kernels =================
// weight transposes (fp16) + bias concat
__global__ __launch_bounds__(256)
void prep_weights_kernel(const float* __restrict__ Wv, const float* __restrict__ Woff,
                         const float* __restrict__ Wattn, const float* __restrict__ Wout,
                         const float* __restrict__ boff, const float* __restrict__ battn)
{
    const int z = blockIdx.z;
    if (z == 4) {
        if (blockIdx.y != 0 || blockIdx.x > 1) return;
        int i = blockIdx.x * 256 + threadIdx.x;
        if (i < NOFF_) g_boa[i] = boff[i];
        else if (i < NOA_) g_boa[i] = battn[i - NOFF_];
        return;
    }
    int R, C; const float* in; long base; int rowOff = 0;
    if (z == 0)      { in = Wv;    R = 256; C = 384; base = WV_OFF; }
    else if (z == 1) { in = Woff;  R = 256; C = 324; base = WOA_OFF; }
    else if (z == 2) { in = Wattn; R = 256; C = 162; base = WOA_OFF; rowOff = 324; }
    else             { in = Wout;  R = 384; C = 256; base = WOUT_OFF; }

    const int c0 = blockIdx.x * 32, r0 = blockIdx.y * 32;
    if (c0 >= C || r0 >= R) return;

    __shared__ float t[32][33];
    const int tx = threadIdx.x & 31, ty = threadIdx.x >> 5;
    #pragma unroll
    for (int i = 0; i < 32; i += 8) {
        int r = r0 + ty + i, c = c0 + tx;
        t[ty + i][tx] = (r < R && c < C) ? in[(long)r * C + c] : 0.f;
    }
    __syncthreads();
    #pragma unroll
    for (int i = 0; i < 32; i += 8) {
        int c = c0 + ty + i, r = r0 + tx;
        if (c < C && r < R)
            g_wh[base + (long)(rowOff + c) * R + r] = __float2half_rn(t[tx][ty + i]);
    }
}

// fused data prep: feature transpose (blocks [0,5040)) + q=x+pe (blocks [5040,9136))
#define FEAT_BLOCKS 5040
#define ADD_N4 (B_*NQ_*DM_/4)       // 1048576
__global__ __launch_bounds__(256)
void prep_data_kernel(const float* __restrict__ x, const float* __restrict__ pe,
                      const float* __restrict__ f0, const float* __restrict__ f1,
                      const float* __restrict__ f2)
{
    const int bx = blockIdx.x;
    if (bx < FEAT_BLOCKS) {
        __shared__ float t[32][33];
        const int b  = bx / 2520;
        int rem = bx - b * 2520;
        const int ry = rem / 315;
        int xt = rem - ry * 315;
        int l, c0;
        const float* in;
        int hwl;
        if (xt < 240)      { l = 0; c0 = xt * 32;         in = f0; hwl = 7680; }
        else if (xt < 300) { l = 1; c0 = (xt - 240) * 32; in = f1; hwl = 1920; }
        else               { l = 2; c0 = (xt - 300) * 32; in = f2; hwl = 480;  }
        in += (long)b * DM_ * hwl;
        const int r0 = ry * 32;
        const int tx = threadIdx.x & 31, ty = threadIdx.x >> 5;

        #pragma unroll
        for (int i = 0; i < 32; i += 8)
            t[ty + i][tx] = in[(long)(r0 + ty + i) * hwl + c0 + tx];
        __syncthreads();
        const long outBase = ((long)b * TOTHW_ + c_OFF[l] + c0) * DM_ + r0;
        #pragma unroll
        for (int i = 0; i < 32; i += 8) {
            long o = outBase + (long)(ty + i) * DM_ + tx;
            g_f16[o] = __float2half_rn(t[tx][ty + i]);
        }
    } else {
        int i = (bx - FEAT_BLOCKS) * 256 + threadIdx.x;
        if (i >= ADD_N4) return;
        float4 a = reinterpret_cast<const float4*>(x)[i];
        float4 b = reinterpret_cast<const float4*>(pe)[i];
        __half h[4];
        h[0] = __float2half_rn(a.x + b.x);
        h[1] = __float2half_rn(a.y + b.y);
        h[2] = __float2half_rn(a.z + b.z);
        h[3] = __float2half_rn(a.w + b.w);
        *reinterpret_cast<uint2*>(g_q16 + (size_t)i*4) = *reinterpret_cast<uint2*>(h);
    }
}

// ================= fp16 tensor-core GEMM (dual-descriptor, single B plane) =================
#define BM 128
#define BN 64
#define BK 32
#define A_TILE_B (BM*BK*2)                 // 8192
#define B_TILE_B (BN*BK*2)                 // 4096
#define STAGE_B  (A_TILE_B + B_TILE_B)     // 12288
#define NSTAGE 3
#define GEMM_SMEM (NSTAGE*STAGE_B)         // 36864

struct GDesc {
    const __half* A;
    const __half* Bh;
    const float*  bias;
    void*         C;
    int M, N, K, halfOut, nbx;
};

#define MMAF16(d, a, b0v, b1v) \
  asm volatile("mma.sync.aligned.m16n8k16.row.col.f32.f16.f16.f32 " \
    "{%0,%1,%2,%3},{%4,%5,%6,%7},{%8,%9},{%0,%1,%2,%3};" \
    : "+f"((d)[0]), "+f"((d)[1]), "+f"((d)[2]), "+f"((d)[3]) \
    : "r"((a)[0]), "r"((a)[1]), "r"((a)[2]), "r"((a)[3]), "r"(b0v), "r"(b1v))

__device__ __forceinline__ uint32_t swz(uint32_t off) {
    return off ^ ((off >> 3) & 0x30);
}
__device__ __forceinline__ void ldsm4(uint32_t (&r)[4], uint32_t addr) {
    asm volatile("ldmatrix.sync.aligned.m8n8.x4.shared.b16 {%0,%1,%2,%3}, [%4];"
        : "=r"(r[0]), "=r"(r[1]), "=r"(r[2]), "=r"(r[3]) : "r"(addr));
}
__device__ __forceinline__ void cp16(uint32_t dst, const void* src, bool pred) {
    int sz = pred ? 16 : 0;
    asm volatile("cp.async.cg.shared.global [%0], [%1], 16, %2;\n"
                 :: "r"(dst), "l"(src), "r"(sz));
}

__global__ __launch_bounds__(128, 4)
void f16_gemm_dual(GDesc d0, GDesc d1, int split)
{
    extern __shared__ uint8_t sm8[];
    uint32_t smb;
    asm("{ .reg .u64 t; cvta.to.shared.u64 t, %1; cvt.u32.u64 %0, t; }" : "=r"(smb) : "l"(sm8));

    const bool first = (int)blockIdx.x < split;
    const GDesc d = first ? d0 : d1;
    const int idx = first ? blockIdx.x : (blockIdx.x - split);
    const int m0 = (idx / d.nbx) * BM;
    const int n0 = (idx % d.nbx) * BN;
    const int M = d.M, N = d.N, K = d.K;

    const int tid = threadIdx.x;
    const int lane = tid & 31, wm = tid >> 5;
    const int r = lane >> 2, cc = lane & 3;

    float acc[2][8][4];
    #pragma unroll
    for (int i = 0; i < 2; i++)
        #pragma unroll
        for (int j = 0; j < 8; j++)
            #pragma unroll
            for (int t = 0; t < 4; t++) acc[i][j][t] = 0.f;

    const int nst = K / BK;

    auto LOAD = [&](int s, int buf) {
        uint32_t base = smb + buf * STAGE_B;
        const int k0 = s * BK;
        #pragma unroll
        for (int i = 0; i < 4; i++) {
            int c = tid + i * 128;
            int row = c >> 2, col = c & 3;
            bool p = (m0 + row) < M;
            long g = (long)(p ? (m0 + row) : 0) * K + k0 + col * 8;
            uint32_t so = swz((uint32_t)(row * 64 + col * 16));
            cp16(base + so, d.A + g, p);
        }
        #pragma unroll
        for (int i = 0; i < 2; i++) {
            int c = tid + i * 128;
            int row = c >> 2, col = c & 3;
            bool p = (n0 + row) < N;
            long g = (long)(p ? (n0 + row) : 0) * K + k0 + col * 8;
            uint32_t so = swz((uint32_t)(row * 64 + col * 16));
            cp16(base + A_TILE_B + so, d.Bh + g, p);
        }
        asm volatile("cp.async.commit_group;\n" ::: "memory");
    };

    auto COMPUTE = [&](int buf) {
        uint32_t base = smb + buf * STAGE_B;
        #pragma unroll
        for (int kk = 0; kk < 2; kk++) {
            const uint32_t koff = (uint32_t)((kk * 2 + (lane >> 4)) * 16);
            uint32_t a[2][4];
            #pragma unroll
            for (int mt = 0; mt < 2; mt++) {
                int row = wm * 32 + mt * 16 + (lane & 15);
                ldsm4(a[mt], base + swz((uint32_t)(row * 64) + koff));
            }
            uint32_t bh[2][4];
            {
                int row = (lane & 15);
                ldsm4(bh[0], base + A_TILE_B + swz((uint32_t)(row * 64) + koff));
            }
            #pragma unroll
            for (int nt2 = 0; nt2 < 4; nt2++) {
                const int cur = nt2 & 1, nxt = cur ^ 1;
                if (nt2 < 3) {
                    int row = (nt2 + 1) * 16 + (lane & 15);
                    ldsm4(bh[nxt], base + A_TILE_B + swz((uint32_t)(row * 64) + koff));
                }
                #pragma unroll
                for (int mt = 0; mt < 2; mt++)
                    #pragma unroll
                    for (int hv = 0; hv < 2; hv++) {
                        int nt = nt2 * 2 + hv;
                        MMAF16(acc[mt][nt], a[mt], bh[cur][hv], bh[cur][hv + 2]);
                    }
            }
        }
    };

    LOAD(0, 0);
    if (nst > 1) LOAD(1, 1);
    for (int s = 0; s < nst; s++) {
        if (s + 1 < nst) { asm volatile("cp.async.wait_group 1;\n" ::: "memory"); }
        else             { asm volatile("cp.async.wait_group 0;\n" ::: "memory"); }
        __syncthreads();
        if (s + 2 < nst) LOAD(s + 2, (s + 2) % NSTAGE);
        COMPUTE(s % NSTAGE);
    }

    if (d.halfOut) {
        __half* C = (__half*)d.C;
        #pragma unroll
        for (int mt = 0; mt < 2; mt++) {
            int m = m0 + wm * 32 + mt * 16 + r;
            #pragma unroll
            for (int nt = 0; nt < 8; nt++) {
                int n = n0 + nt * 8 + cc * 2;
                const float* dd = acc[mt][nt];
                if (n + 1 < N) {
                    float b0 = d.bias[n], b1 = d.bias[n + 1];
                    if (m < M)
                        *(__half2*)&C[(long)m * N + n] = __floats2half2_rn(dd[0] + b0, dd[1] + b1);
                    if (m + 8 < M)
                        *(__half2*)&C[(long)(m + 8) * N + n] = __floats2half2_rn(dd[2] + b0, dd[3] + b1);
                } else if (n < N) {
                    float b0 = d.bias[n];
                    if (m < M)     C[(long)m * N + n]       = __float2half_rn(dd[0] + b0);
                    if (m + 8 < M) C[(long)(m + 8) * N + n] = __float2half_rn(dd[2] + b0);
                }
            }
        }
    } else {
        float* C = (float*)d.C;
        #pragma unroll
        for (int mt = 0; mt < 2; mt++) {
            int m = m0 + wm * 32 + mt * 16 + r;
            #pragma unroll
            for (int nt = 0; nt < 8; nt++) {
                int n = n0 + nt * 8 + cc * 2;
                const float* dd = acc[mt][nt];
                if (m < M) {
                    if (n < N)     C[(long)m * N + n]     = dd[0] + d.bias[n];
                    if (n + 1 < N) C[(long)m * N + n + 1] = dd[1] + d.bias[n + 1];
                }
                if (m + 8 < M) {
                    if (n < N)     C[(long)(m + 8) * N + n]     = dd[2] + d.bias[n];
                    if (n + 1 < N) C[(long)(m + 8) * N + n + 1] = dd[3] + d.bias[n + 1];
                }
            }
        }
    }
}

// ---------------- sampler v5: block=(qchunk, head, batch); level-2 values in smem ----------------
// 256 threads = 8 warps; warp handles 32 queries sequentially.
// Lanes 0..26 own one sample's metadata in registers; gather loop shuffles it out.
// Subgroup g (8 lanes) handles sample j=jp*4+g; levels 0/1 gather from global,
// level 2 (j>=18, incl. pad j=27) from the preloaded smem slice.
#define QPB 256
#define L2PIX 480
#define SAMP_SMEM (L2PIX * DH_ * 2)   // 61440 bytes

__global__ __launch_bounds__(256)
void sample_kernel(const float* __restrict__ coor,
                   const float* __restrict__ cam2img,
                   const float* __restrict__ lidar2cam)
{
    extern __shared__ __half s_v[];
    const int h = blockIdx.y;
    const int b = blockIdx.z;
    const int tid = threadIdx.x;
    const int warp = tid >> 5, lane = tid & 31;
    const int g = lane >> 3, l8 = lane & 7;

    // preload level-2 value slice for (b, h): 480 px x 64 ch fp16
    {
        uint4* dst = reinterpret_cast<uint4*>(s_v);
        const int pbase = b * TOTHW_ + 9600;
        for (int c = tid; c < L2PIX * 8; c += 256) {
            int p = c >> 3, k = c & 7;
            dst[c] = *reinterpret_cast<const uint4*>(
                g_vh16 + ((size_t)(pbase + p) * NHD_) + h * DH_ + k * 8);
        }
    }
    __syncthreads();
    uint32_t svb;
    asm("{ .reg .u64 t; cvta.to.shared.u64 t, %1; cvt.u32.u64 %0, t; }" : "=r"(svb) : "l"(s_v));

    const float* Lm = lidar2cam + b * 16;
    const float* Kc = cam2img + b * 16;
    const int qbase = blockIdx.x * QPB + warp * (QPB / 8);

    for (int qi = 0; qi < QPB / 8; qi++) {
        const int q = qbase + qi;
        const long bq = (long)b * NQ_ + q;

        // projection (all lanes, broadcast loads)
        float p0 = coor[bq*3+0], p1 = coor[bq*3+1], p2 = coor[bq*3+2];
        float pc0 = Lm[0]*p0 + Lm[1]*p1 + Lm[2]*p2  + Lm[3];
        float pc1 = Lm[4]*p0 + Lm[5]*p1 + Lm[6]*p2  + Lm[7];
        float pc2 = Lm[8]*p0 + Lm[9]*p1 + Lm[10]*p2 + Lm[11];
        float pr0 = Kc[0]*pc0 + Kc[1]*pc1 + Kc[2]*pc2  + Kc[3];
        float pr1 = Kc[4]*pc0 + Kc[5]*pc1 + Kc[6]*pc2  + Kc[7];
        float pr2 = Kc[8]*pc0 + Kc[9]*pc1 + Kc[10]*pc2 + Kc[11];
        float uu = pr0 / pr2, vv = pr1 / pr2;

        const float* oa = g_oa + bq * NOA_;
        float lg = -1e30f;
        int   i0 = 0, i1 = 0, i2 = 0, i3 = 0;
        float bw0 = 0.f, bw1 = 0.f, bw2 = 0.f, bw3 = 0.f;
        if (lane < NATT_/NH_) { // lane < 27
            const int j = lane, l = j / 9, p = j - l * 9;
            lg = oa[NOFF_ + h * 27 + j];
            float2 off = *reinterpret_cast<const float2*>(oa + h * 54 + l * 18 + p * 2);
            float px = uu * c_SX[l] + off.x - 0.5f;
            float py = vv * c_SY[l] + off.y - 0.5f;
            float x0f = floorf(px), y0f = floorf(py);
            float fx = px - x0f, fy = py - y0f;
            const int wl = c_W[l], hl = c_H[l];
            int ids[4]; float bws[4];
            #pragma unroll
            for (int c = 0; c < 4; c++) {
                int dx = c & 1, dy = c >> 1;
                float xi = x0f + dx, yi = y0f + dy;
                bool valid = (xi >= 0.f) && (xi < (float)wl) && (yi >= 0.f) && (yi < (float)hl);
                float wgt = (dx ? fx : 1.f - fx) * (dy ? fy : 1.f - fy);
                float xc = fminf(fmaxf(xi, 0.f), (float)(wl - 1));
                float yc = fminf(fmaxf(yi, 0.f), (float)(hl - 1));
                int pix = (int)yc * wl + (int)xc;
                if (l < 2) ids[c] = (b * TOTHW_ + c_OFF[l] + pix) * NHD_ + h * DH_; // global elems
                else       ids[c] = pix * DH_;                                       // smem elems
                bws[c] = valid ? wgt : 0.f;
            }
            i0 = ids[0]; i1 = ids[1]; i2 = ids[2]; i3 = ids[3];
            bw0 = bws[0]; bw1 = bws[1]; bw2 = bws[2]; bw3 = bws[3];
        }

        // softmax over the 27 logits (warp tree; lanes >=27 padded)
        float mx = lg;
        #pragma unroll
        for (int s = 16; s > 0; s >>= 1) mx = fmaxf(mx, __shfl_xor_sync(0xffffffffu, mx, s));
        float w_e = (lane < 27) ? expf(lg - mx) : 0.f;
        float sum = w_e;
        #pragma unroll
        for (int s = 16; s > 0; s >>= 1) sum += __shfl_xor_sync(0xffffffffu, sum, s);
        const float rsum = 1.f / sum;

        float a[8];
        #pragma unroll
        for (int k = 0; k < 8; k++) a[k] = 0.f;

        #pragma unroll
        for (int jp = 0; jp < 7; jp++) {
            const int jsrc = jp * 4 + g;
            const float aw = __shfl_sync(0xffffffffu, w_e, jsrc) * rsum;
            int jj[4];
            jj[0] = __shfl_sync(0xffffffffu, i0, jsrc);
            jj[1] = __shfl_sync(0xffffffffu, i1, jsrc);
            jj[2] = __shfl_sync(0xffffffffu, i2, jsrc);
            jj[3] = __shfl_sync(0xffffffffu, i3, jsrc);
            float cw[4];
            cw[0] = __shfl_sync(0xffffffffu, bw0, jsrc);
            cw[1] = __shfl_sync(0xffffffffu, bw1, jsrc);
            cw[2] = __shfl_sync(0xffffffffu, bw2, jsrc);
            cw[3] = __shfl_sync(0xffffffffu, bw3, jsrc);

            float t[8];
            #pragma unroll
            for (int k = 0; k < 8; k++) t[k] = 0.f;

            if (jsrc < 18) {
                #pragma unroll
                for (int c = 0; c < 4; c++) {
                    uint4 u4 = *reinterpret_cast<const uint4*>(g_vh16 + (size_t)jj[c] + l8 * 8);
                    float w = cw[c];
                    float2 f0 = __half22float2(*reinterpret_cast<__half2*>(&u4.x));
                    float2 f1 = __half22float2(*reinterpret_cast<__half2*>(&u4.y));
                    float2 f2 = __half22float2(*reinterpret_cast<__half2*>(&u4.z));
                    float2 f3 = __half22float2(*reinterpret_cast<__half2*>(&u4.w));
                    t[0] += w * f0.x; t[1] += w * f0.y;
                    t[2] += w * f1.x; t[3] += w * f1.y;
                    t[4] += w * f2.x; t[5] += w * f2.y;
                    t[6] += w * f3.x; t[7] += w * f3.y;
                }
            } else {
                #pragma unroll
                for (int c = 0; c < 4; c++) {
                    uint32_t addr = svb + (uint32_t)(jj[c] * 2) + l8 * 16;
                    uint4 u4;
                    asm volatile("ld.shared.v4.b32 {%0,%1,%2,%3}, [%4];"
                        : "=r"(u4.x), "=r"(u4.y), "=r"(u4.z), "=r"(u4.w) : "r"(addr));
                    float w = cw[c];
                    float2 f0 = __half22float2(*reinterpret_cast<__half2*>(&u4.x));
                    float2 f1 = __half22float2(*reinterpret_cast<__half2*>(&u4.y));
                    float2 f2 = __half22float2(*reinterpret_cast<__half2*>(&u4.z));
                    float2 f3 = __half22float2(*reinterpret_cast<__half2*>(&u4.w));
                    t[0] += w * f0.x; t[1] += w * f0.y;
                    t[2] += w * f1.x; t[3] += w * f1.y;
                    t[4] += w * f2.x; t[5] += w * f2.y;
                    t[6] += w * f3.x; t[7] += w * f3.y;
                }
            }
            #pragma unroll
            for (int k = 0; k < 8; k++) a[k] += aw * t[k];
        }

        #pragma unroll
        for (int k = 0; k < 8; k++) {
            a[k] += __shfl_xor_sync(0xffffffffu, a[k], 8);
            a[k] += __shfl_xor_sync(0xffffffffu, a[k], 16);
        }

        if (g == 0) {
            long oidx = bq * NHD_ + h * DH_ + l8 * 8;
            __half hv[8];
            #pragma unroll
            for (int k = 0; k < 8; k++) hv[k] = __float2half_rn(a[k]);
            *reinterpret_cast<uint4*>(&g_mid16[oidx]) = *reinterpret_cast<uint4*>(hv);
        }
    }
}

// ---------------- host launcher ----------------
extern "C" void kernel_launch(void* const* d_in, const int* in_sizes, int n_in,
                              void* d_out, int out_size)
{
    const float* x         = (const float*)d_in[0];
    const float* pe        = (const float*)d_in[1];
    const float* coor      = (const float*)d_in[2];
    const float* cam2img   = (const float*)d_in[3];
    const float* lidar2cam = (const float*)d_in[4];
    const float* feat0     = (const float*)d_in[5];
    const float* feat1     = (const float*)d_in[6];
    const float* feat2     = (const float*)d_in[7];
    const float* W_value   = (const float*)d_in[8];
    const float* b_value   = (const float*)d_in[9];
    const float* W_off     = (const float*)d_in[10];
    const float* b_off     = (const float*)d_in[11];
    const float* W_attn    = (const float*)d_in[12];
    const float* b_attn    = (const float*)d_in[13];
    const float* W_out     = (const float*)d_in[14];
    const float* b_out     = (const float*)d_in[15];
    float* out = (float*)d_out;

    float *poa, *pboa;
    __half *pv16, *pq16, *pf16, *pmid16, *pwh;
    cudaGetSymbolAddress((void**)&pv16, g_vh16);
    cudaGetSymbolAddress((void**)&poa, g_oa);
    cudaGetSymbolAddress((void**)&pboa, g_boa);
    cudaGetSymbolAddress((void**)&pq16, g_q16);
    cudaGetSymbolAddress((void**)&pf16, g_f16);
    cudaGetSymbolAddress((void**)&pmid16, g_mid16);
    cudaGetSymbolAddress((void**)&pwh, g_wh);

    static bool attrSet = false;
    if (!attrSet) {
        cudaFuncSetAttribute(f16_gemm_dual, cudaFuncAttributeMaxDynamicSharedMemorySize, GEMM_SMEM);
        cudaFuncSetAttribute(sample_kernel, cudaFuncAttributeMaxDynamicSharedMemorySize, SAMP_SMEM);
        attrSet = true;
    }

    // 1: weight transposes + bias concat
    {
        dim3 grid(12, 12, 5);
        prep_weights_kernel<<<grid, 256>>>(W_value, W_off, W_attn, W_out, b_off, b_attn);
    }
    // 2: fused data prep (feature transpose + q = x + pe)
    {
        int nb = FEAT_BLOCKS + (ADD_N4 + 255) / 256;   // 5040 + 4096 = 9136
        prep_data_kernel<<<nb, 256>>>(x, pe, feat0, feat1, feat2);
    }
    // 3: fused value + offsets/attn GEMMs (one launch)
    {
        GDesc dv;  // value: [B*TOTHW, 384] = f16 @ Wv
        dv.A = pf16; dv.Bh = pwh + WV_OFF;
        dv.bias = b_value; dv.C = pv16;
        dv.M = B_ * TOTHW_; dv.N = NHD_; dv.K = DM_; dv.halfOut = 1;
        dv.nbx = NHD_ / BN;  // 6
        int nv = dv.nbx * ((dv.M + BM - 1) / BM);   // 948

        GDesc doa; // offsets+attn: [B*NQ, 486] = q16 @ Woa
        doa.A = pq16; doa.Bh = pwh + WOA_OFF;
        doa.bias = pboa; doa.C = poa;
        doa.M = B_ * NQ_; doa.N = NOA_; doa.K = DM_; doa.halfOut = 0;
        doa.nbx = (NOA_ + BN - 1) / BN;  // 8
        int noa = doa.nbx * (doa.M / BM);            // 1024

        f16_gemm_dual<<<nv + noa, 128, GEMM_SMEM>>>(dv, doa, nv);
    }
    // 4: sampler (per-head blocks, level-2 slice in smem)
    {
        dim3 grid(NQ_ / QPB, NH_, B_);   // (32, 6, 2)
        sample_kernel<<<grid, 256, SAMP_SMEM>>>(coor, cam2img, lidar2cam);
    }
    // 5: output GEMM
    {
        GDesc dn;
        dn.A = pmid16; dn.Bh = pwh + WOUT_OFF;
        dn.bias = b_out; dn.C = out;
        dn.M = B_ * NQ_; dn.N = DM_; dn.K = NHD_; dn.halfOut = 0;
        dn.nbx = DM_ / BN;  // 4
        int nb = dn.nbx * (dn.M / BM);  // 512
        f16_gemm_dual<<<nb, 128, GEMM_SMEM>>>(dn, dn, nb);
    }
}

// round 15
// speedup vs baseline: 1.1515x; 1.1515x over previous
#include <cuda_runtime.h>
#include <cuda_bf16.h>
#include <cuda_fp16.h>
#include <math.h>
#include <stdint.h>

// ---------------- problem constants ----------------
#define B_   2
#define NQ_  8192
#define DM_  256
#define NH_  6
#define DH_  64
#define NL_  3
#define NP_  9
#define NHD_ (NH_*DH_)            // 384
#define NOFF_ (NH_*NL_*NP_*2)     // 324
#define NATT_ (NH_*NL_*NP_)       // 162
#define NOA_  (NOFF_ + NATT_)     // 486
#define TOTHW_ 10080              // 7680+1920+480

// level tables
__device__ __constant__ int   c_W[3]   = {160, 80, 40};
__device__ __constant__ int   c_H[3]   = {48, 24, 12};
__device__ __constant__ int   c_OFF[3] = {0, 7680, 9600};
__device__ __constant__ float c_SX[3]  = {160.f/1280.f, 80.f/1280.f, 40.f/1280.f};
__device__ __constant__ float c_SY[3]  = {48.f/384.f, 24.f/384.f, 12.f/384.f};

// ---------------- scratch (no allocs allowed) ----------------
__device__ __half g_vh16[(size_t)B_ * TOTHW_ * NHD_];   // value projection (fp16)
__device__ float g_oa  [(size_t)B_ * NQ_ * NOA_];       // offsets(324) | attn(162)
__device__ float g_boa [NOA_];

// single fp16 A-planes
__device__ __half g_q16 [(size_t)B_ * NQ_ * DM_];
__device__ __half g_f16 [(size_t)B_ * TOTHW_ * DM_];
__device__ __half g_mid16[(size_t)B_ * NQ_ * NHD_];

// weights transposed [N][K] fp16: Wv(384x256) | Woa(486x256) | Wout(256x384)
#define WV_OFF   0
#define WOA_OFF  (384*256)
#define WOUT_OFF (WOA_OFF + NOA_*256)
#define WTOT_    (WOUT_OFF + 256*384)
__device__ __half g_wh[WTOT_];

// ================= prep kernels =================
// weight transposes (fp16) + bias concat
__global__ __launch_bounds__(256)
void prep_weights_kernel(const float* __restrict__ Wv, const float* __restrict__ Woff,
                         const float* __restrict__ Wattn, const float* __restrict__ Wout,
                         const float* __restrict__ boff, const float* __restrict__ battn)
{
    const int z = blockIdx.z;
    if (z == 4) {
        if (blockIdx.y != 0 || blockIdx.x > 1) return;
        int i = blockIdx.x * 256 + threadIdx.x;
        if (i < NOFF_) g_boa[i] = boff[i];
        else if (i < NOA_) g_boa[i] = battn[i - NOFF_];
        return;
    }
    int R, C; const float* in; long base; int rowOff = 0;
    if (z == 0)      { in = Wv;    R = 256; C = 384; base = WV_OFF; }
    else if (z == 1) { in = Woff;  R = 256; C = 324; base = WOA_OFF; }
    else if (z == 2) { in = Wattn; R = 256; C = 162; base = WOA_OFF; rowOff = 324; }
    else             { in = Wout;  R = 384; C = 256; base = WOUT_OFF; }

    const int c0 = blockIdx.x * 32, r0 = blockIdx.y * 32;
    if (c0 >= C || r0 >= R) return;

    __shared__ float t[32][33];
    const int tx = threadIdx.x & 31, ty = threadIdx.x >> 5;
    #pragma unroll
    for (int i = 0; i < 32; i += 8) {
        int r = r0 + ty + i, c = c0 + tx;
        t[ty + i][tx] = (r < R && c < C) ? in[(long)r * C + c] : 0.f;
    }
    __syncthreads();
    #pragma unroll
    for (int i = 0; i < 32; i += 8) {
        int c = c0 + ty + i, r = r0 + tx;
        if (c < C && r < R)
            g_wh[base + (long)(rowOff + c) * R + r] = __float2half_rn(t[tx][ty + i]);
    }
}

// fused data prep: feature transpose (blocks [0,5040)) + q=x+pe (blocks [5040,9136))
#define FEAT_BLOCKS 5040
#define ADD_N4 (B_*NQ_*DM_/4)       // 1048576
__global__ __launch_bounds__(256)
void prep_data_kernel(const float* __restrict__ x, const float* __restrict__ pe,
                      const float* __restrict__ f0, const float* __restrict__ f1,
                      const float* __restrict__ f2)
{
    const int bx = blockIdx.x;
    if (bx < FEAT_BLOCKS) {
        __shared__ float t[32][33];
        const int b  = bx / 2520;
        int rem = bx - b * 2520;
        const int ry = rem / 315;
        int xt = rem - ry * 315;
        int l, c0;
        const float* in;
        int hwl;
        if (xt < 240)      { l = 0; c0 = xt * 32;         in = f0; hwl = 7680; }
        else if (xt < 300) { l = 1; c0 = (xt - 240) * 32; in = f1; hwl = 1920; }
        else               { l = 2; c0 = (xt - 300) * 32; in = f2; hwl = 480;  }
        in += (long)b * DM_ * hwl;
        const int r0 = ry * 32;
        const int tx = threadIdx.x & 31, ty = threadIdx.x >> 5;

        #pragma unroll
        for (int i = 0; i < 32; i += 8)
            t[ty + i][tx] = in[(long)(r0 + ty + i) * hwl + c0 + tx];
        __syncthreads();
        const long outBase = ((long)b * TOTHW_ + c_OFF[l] + c0) * DM_ + r0;
        #pragma unroll
        for (int i = 0; i < 32; i += 8) {
            long o = outBase + (long)(ty + i) * DM_ + tx;
            g_f16[o] = __float2half_rn(t[tx][ty + i]);
        }
    } else {
        int i = (bx - FEAT_BLOCKS) * 256 + threadIdx.x;
        if (i >= ADD_N4) return;
        float4 a = reinterpret_cast<const float4*>(x)[i];
        float4 b = reinterpret_cast<const float4*>(pe)[i];
        __half h[4];
        h[0] = __float2half_rn(a.x + b.x);
        h[1] = __float2half_rn(a.y + b.y);
        h[2] = __float2half_rn(a.z + b.z);
        h[3] = __float2half_rn(a.w + b.w);
        *reinterpret_cast<uint2*>(g_q16 + (size_t)i*4) = *reinterpret_cast<uint2*>(h);
    }
}

// ================= fp16 tensor-core GEMM (dual-descriptor, single B plane) =================
#define BM 128
#define BN 64
#define BK 32
#define A_TILE_B (BM*BK*2)                 // 8192
#define B_TILE_B (BN*BK*2)                 // 4096
#define STAGE_B  (A_TILE_B + B_TILE_B)     // 12288
#define NSTAGE 3
#define GEMM_SMEM (NSTAGE*STAGE_B)         // 36864

struct GDesc {
    const __half* A;
    const __half* Bh;
    const float*  bias;
    void*         C;
    int M, N, K, halfOut, nbx;
};

#define MMAF16(d, a, b0v, b1v) \
  asm volatile("mma.sync.aligned.m16n8k16.row.col.f32.f16.f16.f32 " \
    "{%0,%1,%2,%3},{%4,%5,%6,%7},{%8,%9},{%0,%1,%2,%3};" \
    : "+f"((d)[0]), "+f"((d)[1]), "+f"((d)[2]), "+f"((d)[3]) \
    : "r"((a)[0]), "r"((a)[1]), "r"((a)[2]), "r"((a)[3]), "r"(b0v), "r"(b1v))

__device__ __forceinline__ uint32_t swz(uint32_t off) {
    return off ^ ((off >> 3) & 0x30);
}
__device__ __forceinline__ void ldsm4(uint32_t (&r)[4], uint32_t addr) {
    asm volatile("ldmatrix.sync.aligned.m8n8.x4.shared.b16 {%0,%1,%2,%3}, [%4];"
        : "=r"(r[0]), "=r"(r[1]), "=r"(r[2]), "=r"(r[3]) : "r"(addr));
}
__device__ __forceinline__ void cp16(uint32_t dst, const void* src, bool pred) {
    int sz = pred ? 16 : 0;
    asm volatile("cp.async.cg.shared.global [%0], [%1], 16, %2;\n"
                 :: "r"(dst), "l"(src), "r"(sz));
}

__global__ __launch_bounds__(128, 4)
void f16_gemm_dual(GDesc d0, GDesc d1, int split)
{
    extern __shared__ uint8_t sm8[];
    uint32_t smb;
    asm("{ .reg .u64 t; cvta.to.shared.u64 t, %1; cvt.u32.u64 %0, t; }" : "=r"(smb) : "l"(sm8));

    const bool first = (int)blockIdx.x < split;
    const GDesc d = first ? d0 : d1;
    const int idx = first ? blockIdx.x : (blockIdx.x - split);
    const int m0 = (idx / d.nbx) * BM;
    const int n0 = (idx % d.nbx) * BN;
    const int M = d.M, N = d.N, K = d.K;

    const int tid = threadIdx.x;
    const int lane = tid & 31, wm = tid >> 5;
    const int r = lane >> 2, cc = lane & 3;

    float acc[2][8][4];
    #pragma unroll
    for (int i = 0; i < 2; i++)
        #pragma unroll
        for (int j = 0; j < 8; j++)
            #pragma unroll
            for (int t = 0; t < 4; t++) acc[i][j][t] = 0.f;

    const int nst = K / BK;

    auto LOAD = [&](int s, int buf) {
        uint32_t base = smb + buf * STAGE_B;
        const int k0 = s * BK;
        #pragma unroll
        for (int i = 0; i < 4; i++) {
            int c = tid + i * 128;
            int row = c >> 2, col = c & 3;
            bool p = (m0 + row) < M;
            long g = (long)(p ? (m0 + row) : 0) * K + k0 + col * 8;
            uint32_t so = swz((uint32_t)(row * 64 + col * 16));
            cp16(base + so, d.A + g, p);
        }
        #pragma unroll
        for (int i = 0; i < 2; i++) {
            int c = tid + i * 128;
            int row = c >> 2, col = c & 3;
            bool p = (n0 + row) < N;
            long g = (long)(p ? (n0 + row) : 0) * K + k0 + col * 8;
            uint32_t so = swz((uint32_t)(row * 64 + col * 16));
            cp16(base + A_TILE_B + so, d.Bh + g, p);
        }
        asm volatile("cp.async.commit_group;\n" ::: "memory");
    };

    auto COMPUTE = [&](int buf) {
        uint32_t base = smb + buf * STAGE_B;
        #pragma unroll
        for (int kk = 0; kk < 2; kk++) {
            const uint32_t koff = (uint32_t)((kk * 2 + (lane >> 4)) * 16);
            uint32_t a[2][4];
            #pragma unroll
            for (int mt = 0; mt < 2; mt++) {
                int row = wm * 32 + mt * 16 + (lane & 15);
                ldsm4(a[mt], base + swz((uint32_t)(row * 64) + koff));
            }
            uint32_t bh[2][4];
            {
                int row = (lane & 15);
                ldsm4(bh[0], base + A_TILE_B + swz((uint32_t)(row * 64) + koff));
            }
            #pragma unroll
            for (int nt2 = 0; nt2 < 4; nt2++) {
                const int cur = nt2 & 1, nxt = cur ^ 1;
                if (nt2 < 3) {
                    int row = (nt2 + 1) * 16 + (lane & 15);
                    ldsm4(bh[nxt], base + A_TILE_B + swz((uint32_t)(row * 64) + koff));
                }
                #pragma unroll
                for (int mt = 0; mt < 2; mt++)
                    #pragma unroll
                    for (int hv = 0; hv < 2; hv++) {
                        int nt = nt2 * 2 + hv;
                        MMAF16(acc[mt][nt], a[mt], bh[cur][hv], bh[cur][hv + 2]);
                    }
            }
        }
    };

    LOAD(0, 0);
    if (nst > 1) LOAD(1, 1);
    for (int s = 0; s < nst; s++) {
        if (s + 1 < nst) { asm volatile("cp.async.wait_group 1;\n" ::: "memory"); }
        else             { asm volatile("cp.async.wait_group 0;\n" ::: "memory"); }
        __syncthreads();
        if (s + 2 < nst) LOAD(s + 2, (s + 2) % NSTAGE);
        COMPUTE(s % NSTAGE);
    }

    if (d.halfOut) {
        __half* C = (__half*)d.C;
        #pragma unroll
        for (int mt = 0; mt < 2; mt++) {
            int m = m0 + wm * 32 + mt * 16 + r;
            #pragma unroll
            for (int nt = 0; nt < 8; nt++) {
                int n = n0 + nt * 8 + cc * 2;
                const float* dd = acc[mt][nt];
                if (n + 1 < N) {
                    float b0 = d.bias[n], b1 = d.bias[n + 1];
                    if (m < M)
                        *(__half2*)&C[(long)m * N + n] = __floats2half2_rn(dd[0] + b0, dd[1] + b1);
                    if (m + 8 < M)
                        *(__half2*)&C[(long)(m + 8) * N + n] = __floats2half2_rn(dd[2] + b0, dd[3] + b1);
                } else if (n < N) {
                    float b0 = d.bias[n];
                    if (m < M)     C[(long)m * N + n]       = __float2half_rn(dd[0] + b0);
                    if (m + 8 < M) C[(long)(m + 8) * N + n] = __float2half_rn(dd[2] + b0);
                }
            }
        }
    } else {
        float* C = (float*)d.C;
        #pragma unroll
        for (int mt = 0; mt < 2; mt++) {
            int m = m0 + wm * 32 + mt * 16 + r;
            #pragma unroll
            for (int nt = 0; nt < 8; nt++) {
                int n = n0 + nt * 8 + cc * 2;
                const float* dd = acc[mt][nt];
                if (m < M) {
                    if (n < N)     C[(long)m * N + n]     = dd[0] + d.bias[n];
                    if (n + 1 < N) C[(long)m * N + n + 1] = dd[1] + d.bias[n + 1];
                }
                if (m + 8 < M) {
                    if (n < N)     C[(long)(m + 8) * N + n]     = dd[2] + d.bias[n];
                    if (n + 1 < N) C[(long)(m + 8) * N + n + 1] = dd[3] + d.bias[n + 1];
                }
            }
        }
    }
}

// ---------------- sampler v4 + zero-weight corner skip ----------------
// 192 threads: warp = head. lane = g*8 + l8: subgroup g (0..3) owns sample j = jp*4+g,
// lane loads 8 fp16 channels (uint4, 16B; 8 lanes -> 128B aligned wavefront).
// Corner loads predicated on bilinear weight != 0 (subgroup-uniform branch):
// fully out-of-image samples (~20-25%) and the pad sample skip all L2 traffic.
__global__ __launch_bounds__(192)
void sample_kernel(const float* __restrict__ coor,
                   const float* __restrict__ cam2img,
                   const float* __restrict__ lidar2cam)
{
    const int q = blockIdx.x;
    const int b = blockIdx.y;
    const int tid = threadIdx.x;
    const int h    = tid >> 5;
    const int lane = tid & 31;
    const int g    = lane >> 3;
    const int l8   = lane & 7;

    __shared__ float  s_uv[2];
    __shared__ float  s_logit[NH_][NL_*NP_];
    __shared__ float  s_w[NH_][28];
    __shared__ int4   s_idx[NH_][28];
    __shared__ float4 s_bw[NH_][28];

    if (tid == 0) {
        const float* L  = lidar2cam + b * 16;
        const float* Kc = cam2img + b * 16;
        float p0 = coor[((long)b * NQ_ + q) * 3 + 0];
        float p1 = coor[((long)b * NQ_ + q) * 3 + 1];
        float p2 = coor[((long)b * NQ_ + q) * 3 + 2];
        float pc[3], pr[3];
        #pragma unroll
        for (int i = 0; i < 3; i++)
            pc[i] = L[i*4+0]*p0 + L[i*4+1]*p1 + L[i*4+2]*p2 + L[i*4+3];
        #pragma unroll
        for (int i = 0; i < 3; i++)
            pr[i] = Kc[i*4+0]*pc[0] + Kc[i*4+1]*pc[1] + Kc[i*4+2]*pc[2] + Kc[i*4+3];
        s_uv[0] = pr[0] / pr[2];
        s_uv[1] = pr[1] / pr[2];
    }
    __syncthreads();

    const long bq = (long)b * NQ_ + q;
    const float* oa = g_oa + bq * NOA_;

    if (tid < NATT_) {
        const int hh = tid / (NL_*NP_);
        const int j  = tid - hh * (NL_*NP_);
        const int l = j / NP_;
        const int p = j - l * NP_;

        s_logit[hh][j] = oa[NOFF_ + hh * (NL_*NP_) + j];

        const float* offp = &oa[hh * (NL_*NP_*2) + l * (NP_*2) + p * 2];
        float px = s_uv[0] * c_SX[l] + offp[0] - 0.5f;
        float py = s_uv[1] * c_SY[l] + offp[1] - 0.5f;
        float x0 = floorf(px), y0 = floorf(py);
        float fx = px - x0, fy = py - y0;
        const int wl = c_W[l], hl = c_H[l];
        const int base_l = b * TOTHW_ + c_OFF[l];

        int   idv[4];
        float bwv[4];
        #pragma unroll
        for (int c = 0; c < 4; c++) {
            int dx = c & 1, dy = c >> 1;
            float xi = x0 + dx, yi = y0 + dy;
            bool valid = (xi >= 0.f) && (xi < (float)wl) && (yi >= 0.f) && (yi < (float)hl);
            float wgt = (dx ? fx : 1.f - fx) * (dy ? fy : 1.f - fy);
            float xc = fminf(fmaxf(xi, 0.f), (float)(wl - 1));
            float yc = fminf(fmaxf(yi, 0.f), (float)(hl - 1));
            int pix = (int)yc * wl + (int)xc;
            idv[c] = (base_l + pix) * NHD_ + hh * DH_;
            bwv[c] = valid ? wgt : 0.f;
        }
        s_idx[hh][j] = make_int4(idv[0], idv[1], idv[2], idv[3]);
        s_bw[hh][j]  = make_float4(bwv[0], bwv[1], bwv[2], bwv[3]);
    }
    __syncthreads();

    if (tid < NATT_) {
        const int hh = tid / (NL_*NP_);
        const int j  = tid - hh * (NL_*NP_);
        float mx = -1e30f;
        #pragma unroll
        for (int jj = 0; jj < NL_*NP_; jj++) mx = fmaxf(mx, s_logit[hh][jj]);
        s_w[hh][j] = expf(s_logit[hh][j] - mx);
    }
    if (tid < NH_) {
        s_w[tid][27]   = 0.f;
        s_idx[tid][27] = s_idx[tid][26];
        s_bw[tid][27]  = make_float4(0.f, 0.f, 0.f, 0.f);
    }
    __syncthreads();

    float sum = 0.f;
    #pragma unroll
    for (int jj = 0; jj < NL_*NP_; jj++) sum += s_w[h][jj];
    const float rsum = 1.f / sum;

    float a[8];
    #pragma unroll
    for (int k = 0; k < 8; k++) a[k] = 0.f;

    #pragma unroll
    for (int jp = 0; jp < 7; jp++) {
        const int j = jp * 4 + g;
        const float aw = s_w[h][j] * rsum;
        const int4   id = s_idx[h][j];
        const float4 bw = s_bw[h][j];
        const int ids[4] = {id.x, id.y, id.z, id.w};
        const float bws[4] = {bw.x, bw.y, bw.z, bw.w};
        float t[8];
        #pragma unroll
        for (int k = 0; k < 8; k++) t[k] = 0.f;
        #pragma unroll
        for (int c = 0; c < 4; c++) {
            float w = bws[c];
            if (w != 0.f) {   // subgroup-uniform: skips L2 traffic for OOB corners + pad
                uint4 u = *reinterpret_cast<const uint4*>(g_vh16 + ids[c] + l8 * 8);
                float2 f0 = __half22float2(*reinterpret_cast<__half2*>(&u.x));
                float2 f1 = __half22float2(*reinterpret_cast<__half2*>(&u.y));
                float2 f2 = __half22float2(*reinterpret_cast<__half2*>(&u.z));
                float2 f3 = __half22float2(*reinterpret_cast<__half2*>(&u.w));
                t[0] += w * f0.x; t[1] += w * f0.y;
                t[2] += w * f1.x; t[3] += w * f1.y;
                t[4] += w * f2.x; t[5] += w * f2.y;
                t[6] += w * f3.x; t[7] += w * f3.y;
            }
        }
        #pragma unroll
        for (int k = 0; k < 8; k++) a[k] += aw * t[k];
    }

    #pragma unroll
    for (int k = 0; k < 8; k++) {
        a[k] += __shfl_xor_sync(0xffffffffu, a[k], 8);
        a[k] += __shfl_xor_sync(0xffffffffu, a[k], 16);
    }

    if (g == 0) {
        long oidx = bq * NHD_ + h * DH_ + l8 * 8;
        __half hv[8];
        #pragma unroll
        for (int k = 0; k < 8; k++) hv[k] = __float2half_rn(a[k]);
        *reinterpret_cast<uint4*>(&g_mid16[oidx]) = *reinterpret_cast<uint4*>(hv);
    }
}

// ---------------- host launcher ----------------
extern "C" void kernel_launch(void* const* d_in, const int* in_sizes, int n_in,
                              void* d_out, int out_size)
{
    const float* x         = (const float*)d_in[0];
    const float* pe        = (const float*)d_in[1];
    const float* coor      = (const float*)d_in[2];
    const float* cam2img   = (const float*)d_in[3];
    const float* lidar2cam = (const float*)d_in[4];
    const float* feat0     = (const float*)d_in[5];
    const float* feat1     = (const float*)d_in[6];
    const float* feat2     = (const float*)d_in[7];
    const float* W_value   = (const float*)d_in[8];
    const float* b_value   = (const float*)d_in[9];
    const float* W_off     = (const float*)d_in[10];
    const float* b_off     = (const float*)d_in[11];
    const float* W_attn    = (const float*)d_in[12];
    const float* b_attn    = (const float*)d_in[13];
    const float* W_out     = (const float*)d_in[14];
    const float* b_out     = (const float*)d_in[15];
    float* out = (float*)d_out;

    float *poa, *pboa;
    __half *pv16, *pq16, *pf16, *pmid16, *pwh;
    cudaGetSymbolAddress((void**)&pv16, g_vh16);
    cudaGetSymbolAddress((void**)&poa, g_oa);
    cudaGetSymbolAddress((void**)&pboa, g_boa);
    cudaGetSymbolAddress((void**)&pq16, g_q16);
    cudaGetSymbolAddress((void**)&pf16, g_f16);
    cudaGetSymbolAddress((void**)&pmid16, g_mid16);
    cudaGetSymbolAddress((void**)&pwh, g_wh);

    static bool attrSet = false;
    if (!attrSet) {
        cudaFuncSetAttribute(f16_gemm_dual, cudaFuncAttributeMaxDynamicSharedMemorySize, GEMM_SMEM);
        attrSet = true;
    }

    // 1: weight transposes + bias concat
    {
        dim3 grid(12, 12, 5);
        prep_weights_kernel<<<grid, 256>>>(W_value, W_off, W_attn, W_out, b_off, b_attn);
    }
    // 2: fused data prep (feature transpose + q = x + pe)
    {
        int nb = FEAT_BLOCKS + (ADD_N4 + 255) / 256;   // 9136
        prep_data_kernel<<<nb, 256>>>(x, pe, feat0, feat1, feat2);
    }
    // 3: fused value + offsets/attn GEMMs (one launch)
    {
        GDesc dv;  // value: [B*TOTHW, 384] = f16 @ Wv
        dv.A = pf16; dv.Bh = pwh + WV_OFF;
        dv.bias = b_value; dv.C = pv16;
        dv.M = B_ * TOTHW_; dv.N = NHD_; dv.K = DM_; dv.halfOut = 1;
        dv.nbx = NHD_ / BN;  // 6
        int nv = dv.nbx * ((dv.M + BM - 1) / BM);   // 948

        GDesc doa; // offsets+attn: [B*NQ, 486] = q16 @ Woa
        doa.A = pq16; doa.Bh = pwh + WOA_OFF;
        doa.bias = pboa; doa.C = poa;
        doa.M = B_ * NQ_; doa.N = NOA_; doa.K = DM_; doa.halfOut = 0;
        doa.nbx = (NOA_ + BN - 1) / BN;  // 8
        int noa = doa.nbx * (doa.M / BM);            // 1024

        f16_gemm_dual<<<nv + noa, 128, GEMM_SMEM>>>(dv, doa, nv);
    }
    // 4: sampler (v4 + OOB corner skip)
    {
        dim3 grid(NQ_, B_);
        sample_kernel<<<grid, 192>>>(coor, cam2img, lidar2cam);
    }
    // 5: output GEMM
    {
        GDesc dn;
        dn.A = pmid16; dn.Bh = pwh + WOUT_OFF;
        dn.bias = b_out; dn.C = out;
        dn.M = B_ * NQ_; dn.N = DM_; dn.K = NHD_; dn.halfOut = 0;
        dn.nbx = DM_ / BN;  // 4
        int nb = dn.nbx * (dn.M / BM);  // 512
        f16_gemm_dual<<<nb, 128, GEMM_SMEM>>>(dn, dn, nb);
    }
}

// round 16
// speedup vs baseline: 1.2248x; 1.0637x over previous
#include <cuda_runtime.h>
#include <cuda_bf16.h>
#include <cuda_fp16.h>
#include <math.h>
#include <stdint.h>

// ---------------- problem constants ----------------
#define B_   2
#define NQ_  8192
#define DM_  256
#define NH_  6
#define DH_  64
#define NL_  3
#define NP_  9
#define NHD_ (NH_*DH_)            // 384
#define NOFF_ (NH_*NL_*NP_*2)     // 324
#define NATT_ (NH_*NL_*NP_)       // 162
#define NOA_  (NOFF_ + NATT_)     // 486
#define TOTHW_ 10080              // 7680+1920+480

// level tables
__device__ __constant__ int   c_W[3]   = {160, 80, 40};
__device__ __constant__ int   c_H[3]   = {48, 24, 12};
__device__ __constant__ int   c_OFF[3] = {0, 7680, 9600};
__device__ __constant__ float c_SX[3]  = {160.f/1280.f, 80.f/1280.f, 40.f/1280.f};
__device__ __constant__ float c_SY[3]  = {48.f/384.f, 24.f/384.f, 12.f/384.f};

// ---------------- scratch (no allocs allowed) ----------------
__device__ __half g_vh16[(size_t)B_ * TOTHW_ * NHD_];   // value projection (fp16)
__device__ float g_oa  [(size_t)B_ * NQ_ * NOA_];       // offsets(324) | attn(162)
__device__ float g_boa [NOA_];

// single fp16 A-planes
__device__ __half g_q16 [(size_t)B_ * NQ_ * DM_];
__device__ __half g_f16 [(size_t)B_ * TOTHW_ * DM_];
__device__ __half g_mid16[(size_t)B_ * NQ_ * NHD_];

// weights transposed [N][K] fp16: Wv(384x256) | Woa(486x256) | Wout(256x384)
#define WV_OFF   0
#define WOA_OFF  (384*256)
#define WOUT_OFF (WOA_OFF + NOA_*256)
#define WTOT_    (WOUT_OFF + 256*384)
__device__ __half g_wh[WTOT_];

// ================= prep kernels =================
// weight transposes (fp16) + bias concat
__global__ __launch_bounds__(256)
void prep_weights_kernel(const float* __restrict__ Wv, const float* __restrict__ Woff,
                         const float* __restrict__ Wattn, const float* __restrict__ Wout,
                         const float* __restrict__ boff, const float* __restrict__ battn)
{
    const int z = blockIdx.z;
    if (z == 4) {
        if (blockIdx.y != 0 || blockIdx.x > 1) return;
        int i = blockIdx.x * 256 + threadIdx.x;
        if (i < NOFF_) g_boa[i] = boff[i];
        else if (i < NOA_) g_boa[i] = battn[i - NOFF_];
        return;
    }
    int R, C; const float* in; long base; int rowOff = 0;
    if (z == 0)      { in = Wv;    R = 256; C = 384; base = WV_OFF; }
    else if (z == 1) { in = Woff;  R = 256; C = 324; base = WOA_OFF; }
    else if (z == 2) { in = Wattn; R = 256; C = 162; base = WOA_OFF; rowOff = 324; }
    else             { in = Wout;  R = 384; C = 256; base = WOUT_OFF; }

    const int c0 = blockIdx.x * 32, r0 = blockIdx.y * 32;
    if (c0 >= C || r0 >= R) return;

    __shared__ float t[32][33];
    const int tx = threadIdx.x & 31, ty = threadIdx.x >> 5;
    #pragma unroll
    for (int i = 0; i < 32; i += 8) {
        int r = r0 + ty + i, c = c0 + tx;
        t[ty + i][tx] = (r < R && c < C) ? in[(long)r * C + c] : 0.f;
    }
    __syncthreads();
    #pragma unroll
    for (int i = 0; i < 32; i += 8) {
        int c = c0 + ty + i, r = r0 + tx;
        if (c < C && r < R)
            g_wh[base + (long)(rowOff + c) * R + r] = __float2half_rn(t[tx][ty + i]);
    }
}

// fused data prep: feature transpose (blocks [0,5040)) + q=x+pe (blocks [5040,9136))
#define FEAT_BLOCKS 5040
#define ADD_N4 (B_*NQ_*DM_/4)       // 1048576
__global__ __launch_bounds__(256)
void prep_data_kernel(const float* __restrict__ x, const float* __restrict__ pe,
                      const float* __restrict__ f0, const float* __restrict__ f1,
                      const float* __restrict__ f2)
{
    const int bx = blockIdx.x;
    if (bx < FEAT_BLOCKS) {
        __shared__ float t[32][33];
        const int b  = bx / 2520;
        int rem = bx - b * 2520;
        const int ry = rem / 315;
        int xt = rem - ry * 315;
        int l, c0;
        const float* in;
        int hwl;
        if (xt < 240)      { l = 0; c0 = xt * 32;         in = f0; hwl = 7680; }
        else if (xt < 300) { l = 1; c0 = (xt - 240) * 32; in = f1; hwl = 1920; }
        else               { l = 2; c0 = (xt - 300) * 32; in = f2; hwl = 480;  }
        in += (long)b * DM_ * hwl;
        const int r0 = ry * 32;
        const int tx = threadIdx.x & 31, ty = threadIdx.x >> 5;

        #pragma unroll
        for (int i = 0; i < 32; i += 8)
            t[ty + i][tx] = in[(long)(r0 + ty + i) * hwl + c0 + tx];
        __syncthreads();
        const long outBase = ((long)b * TOTHW_ + c_OFF[l] + c0) * DM_ + r0;
        #pragma unroll
        for (int i = 0; i < 32; i += 8) {
            long o = outBase + (long)(ty + i) * DM_ + tx;
            g_f16[o] = __float2half_rn(t[tx][ty + i]);
        }
    } else {
        int i = (bx - FEAT_BLOCKS) * 256 + threadIdx.x;
        if (i >= ADD_N4) return;
        float4 a = reinterpret_cast<const float4*>(x)[i];
        float4 b = reinterpret_cast<const float4*>(pe)[i];
        __half h[4];
        h[0] = __float2half_rn(a.x + b.x);
        h[1] = __float2half_rn(a.y + b.y);
        h[2] = __float2half_rn(a.z + b.z);
        h[3] = __float2half_rn(a.w + b.w);
        *reinterpret_cast<uint2*>(g_q16 + (size_t)i*4) = *reinterpret_cast<uint2*>(h);
    }
}

// ================= fp16 tensor-core GEMM (dual-descriptor, single B plane) =================
#define BM 128
#define BN 64
#define BK 32
#define A_TILE_B (BM*BK*2)                 // 8192
#define B_TILE_B (BN*BK*2)                 // 4096
#define STAGE_B  (A_TILE_B + B_TILE_B)     // 12288
#define NSTAGE 3
#define GEMM_SMEM (NSTAGE*STAGE_B)         // 36864

struct GDesc {
    const __half* A;
    const __half* Bh;
    const float*  bias;
    void*         C;
    int M, N, K, halfOut, nbx;
};

#define MMAF16(d, a, b0v, b1v) \
  asm volatile("mma.sync.aligned.m16n8k16.row.col.f32.f16.f16.f32 " \
    "{%0,%1,%2,%3},{%4,%5,%6,%7},{%8,%9},{%0,%1,%2,%3};" \
    : "+f"((d)[0]), "+f"((d)[1]), "+f"((d)[2]), "+f"((d)[3]) \
    : "r"((a)[0]), "r"((a)[1]), "r"((a)[2]), "r"((a)[3]), "r"(b0v), "r"(b1v))

__device__ __forceinline__ uint32_t swz(uint32_t off) {
    return off ^ ((off >> 3) & 0x30);
}
__device__ __forceinline__ void ldsm4(uint32_t (&r)[4], uint32_t addr) {
    asm volatile("ldmatrix.sync.aligned.m8n8.x4.shared.b16 {%0,%1,%2,%3}, [%4];"
        : "=r"(r[0]), "=r"(r[1]), "=r"(r[2]), "=r"(r[3]) : "r"(addr));
}
__device__ __forceinline__ void cp16(uint32_t dst, const void* src, bool pred) {
    int sz = pred ? 16 : 0;
    asm volatile("cp.async.cg.shared.global [%0], [%1], 16, %2;\n"
                 :: "r"(dst), "l"(src), "r"(sz));
}

__global__ __launch_bounds__(128, 4)
void f16_gemm_dual(GDesc d0, GDesc d1, int split)
{
    extern __shared__ uint8_t sm8[];
    uint32_t smb;
    asm("{ .reg .u64 t; cvta.to.shared.u64 t, %1; cvt.u32.u64 %0, t; }" : "=r"(smb) : "l"(sm8));

    const bool first = (int)blockIdx.x < split;
    const GDesc d = first ? d0 : d1;
    const int idx = first ? blockIdx.x : (blockIdx.x - split);
    const int m0 = (idx / d.nbx) * BM;
    const int n0 = (idx % d.nbx) * BN;
    const int M = d.M, N = d.N, K = d.K;

    const int tid = threadIdx.x;
    const int lane = tid & 31, wm = tid >> 5;
    const int r = lane >> 2, cc = lane & 3;

    float acc[2][8][4];
    #pragma unroll
    for (int i = 0; i < 2; i++)
        #pragma unroll
        for (int j = 0; j < 8; j++)
            #pragma unroll
            for (int t = 0; t < 4; t++) acc[i][j][t] = 0.f;

    const int nst = K / BK;

    auto LOAD = [&](int s, int buf) {
        uint32_t base = smb + buf * STAGE_B;
        const int k0 = s * BK;
        #pragma unroll
        for (int i = 0; i < 4; i++) {
            int c = tid + i * 128;
            int row = c >> 2, col = c & 3;
            bool p = (m0 + row) < M;
            long g = (long)(p ? (m0 + row) : 0) * K + k0 + col * 8;
            uint32_t so = swz((uint32_t)(row * 64 + col * 16));
            cp16(base + so, d.A + g, p);
        }
        #pragma unroll
        for (int i = 0; i < 2; i++) {
            int c = tid + i * 128;
            int row = c >> 2, col = c & 3;
            bool p = (n0 + row) < N;
            long g = (long)(p ? (n0 + row) : 0) * K + k0 + col * 8;
            uint32_t so = swz((uint32_t)(row * 64 + col * 16));
            cp16(base + A_TILE_B + so, d.Bh + g, p);
        }
        asm volatile("cp.async.commit_group;\n" ::: "memory");
    };

    auto COMPUTE = [&](int buf) {
        uint32_t base = smb + buf * STAGE_B;
        #pragma unroll
        for (int kk = 0; kk < 2; kk++) {
            const uint32_t koff = (uint32_t)((kk * 2 + (lane >> 4)) * 16);
            uint32_t a[2][4];
            #pragma unroll
            for (int mt = 0; mt < 2; mt++) {
                int row = wm * 32 + mt * 16 + (lane & 15);
                ldsm4(a[mt], base + swz((uint32_t)(row * 64) + koff));
            }
            uint32_t bh[2][4];
            {
                int row = (lane & 15);
                ldsm4(bh[0], base + A_TILE_B + swz((uint32_t)(row * 64) + koff));
            }
            #pragma unroll
            for (int nt2 = 0; nt2 < 4; nt2++) {
                const int cur = nt2 & 1, nxt = cur ^ 1;
                if (nt2 < 3) {
                    int row = (nt2 + 1) * 16 + (lane & 15);
                    ldsm4(bh[nxt], base + A_TILE_B + swz((uint32_t)(row * 64) + koff));
                }
                #pragma unroll
                for (int mt = 0; mt < 2; mt++)
                    #pragma unroll
                    for (int hv = 0; hv < 2; hv++) {
                        int nt = nt2 * 2 + hv;
                        MMAF16(acc[mt][nt], a[mt], bh[cur][hv], bh[cur][hv + 2]);
                    }
            }
        }
    };

    LOAD(0, 0);
    if (nst > 1) LOAD(1, 1);
    for (int s = 0; s < nst; s++) {
        if (s + 1 < nst) { asm volatile("cp.async.wait_group 1;\n" ::: "memory"); }
        else             { asm volatile("cp.async.wait_group 0;\n" ::: "memory"); }
        __syncthreads();
        if (s + 2 < nst) LOAD(s + 2, (s + 2) % NSTAGE);
        COMPUTE(s % NSTAGE);
    }

    if (d.halfOut) {
        __half* C = (__half*)d.C;
        #pragma unroll
        for (int mt = 0; mt < 2; mt++) {
            int m = m0 + wm * 32 + mt * 16 + r;
            #pragma unroll
            for (int nt = 0; nt < 8; nt++) {
                int n = n0 + nt * 8 + cc * 2;
                const float* dd = acc[mt][nt];
                if (n + 1 < N) {
                    float b0 = d.bias[n], b1 = d.bias[n + 1];
                    if (m < M)
                        *(__half2*)&C[(long)m * N + n] = __floats2half2_rn(dd[0] + b0, dd[1] + b1);
                    if (m + 8 < M)
                        *(__half2*)&C[(long)(m + 8) * N + n] = __floats2half2_rn(dd[2] + b0, dd[3] + b1);
                } else if (n < N) {
                    float b0 = d.bias[n];
                    if (m < M)     C[(long)m * N + n]       = __float2half_rn(dd[0] + b0);
                    if (m + 8 < M) C[(long)(m + 8) * N + n] = __float2half_rn(dd[2] + b0);
                }
            }
        }
    } else {
        float* C = (float*)d.C;
        #pragma unroll
        for (int mt = 0; mt < 2; mt++) {
            int m = m0 + wm * 32 + mt * 16 + r;
            #pragma unroll
            for (int nt = 0; nt < 8; nt++) {
                int n = n0 + nt * 8 + cc * 2;
                const float* dd = acc[mt][nt];
                if (m < M) {
                    if (n < N)     C[(long)m * N + n]     = dd[0] + d.bias[n];
                    if (n + 1 < N) C[(long)m * N + n + 1] = dd[1] + d.bias[n + 1];
                }
                if (m + 8 < M) {
                    if (n < N)     C[(long)(m + 8) * N + n]     = dd[2] + d.bias[n];
                    if (n + 1 < N) C[(long)(m + 8) * N + n + 1] = dd[3] + d.bias[n + 1];
                }
            }
        }
    }
}

// ---------------- sampler v6: pre-fused weights, byte-offset indices, no branches ----------------
// 192 threads: warp = head; subgroup g (8 lanes) owns sample j = jp*4+g; lane loads
// 8 fp16 channels (uint4). Metadata phase pre-multiplies softmax weight into the 4
// bilinear corner weights, so the gather loop is pure  a[k] += wc * v  (no staging,
// no attention-weight LDS/mul, no branches). Indices stored as byte offsets.
__global__ __launch_bounds__(192)
void sample_kernel(const float* __restrict__ coor,
                   const float* __restrict__ cam2img,
                   const float* __restrict__ lidar2cam)
{
    const int q = blockIdx.x;
    const int b = blockIdx.y;
    const int tid = threadIdx.x;
    const int h    = tid >> 5;
    const int lane = tid & 31;
    const int g    = lane >> 3;
    const int l8   = lane & 7;

    __shared__ float  s_uv[2];
    __shared__ float  s_logit[NH_][NL_*NP_];
    __shared__ float  s_e[NH_][NL_*NP_];
    __shared__ int4   s_idx[NH_][28];     // byte offsets into g_vh16
    __shared__ float4 s_wb[NH_][28];      // softmax * bilinear, pre-fused

    // projection (one thread)
    if (tid == 0) {
        const float* L  = lidar2cam + b * 16;
        const float* Kc = cam2img + b * 16;
        float p0 = coor[((long)b * NQ_ + q) * 3 + 0];
        float p1 = coor[((long)b * NQ_ + q) * 3 + 1];
        float p2 = coor[((long)b * NQ_ + q) * 3 + 2];
        float pc[3], pr[3];
        #pragma unroll
        for (int i = 0; i < 3; i++)
            pc[i] = L[i*4+0]*p0 + L[i*4+1]*p1 + L[i*4+2]*p2 + L[i*4+3];
        #pragma unroll
        for (int i = 0; i < 3; i++)
            pr[i] = Kc[i*4+0]*pc[0] + Kc[i*4+1]*pc[1] + Kc[i*4+2]*pc[2] + Kc[i*4+3];
        s_uv[0] = pr[0] / pr[2];
        s_uv[1] = pr[1] / pr[2];
    }

    const long bq = (long)b * NQ_ + q;
    const float* oa = g_oa + bq * NOA_;

    // phase 1: logits -> smem
    if (tid < NATT_) {
        const int hh = tid / (NL_*NP_);
        const int j  = tid - hh * (NL_*NP_);
        s_logit[hh][j] = oa[NOFF_ + hh * (NL_*NP_) + j];
    }
    __syncthreads();

    // phase 2: exp(l - max)
    if (tid < NATT_) {
        const int hh = tid / (NL_*NP_);
        const int j  = tid - hh * (NL_*NP_);
        float mx = -1e30f;
        #pragma unroll
        for (int jj = 0; jj < NL_*NP_; jj++) mx = fmaxf(mx, s_logit[hh][jj]);
        s_e[hh][j] = expf(s_logit[hh][j] - mx);
    }
    __syncthreads();

    // phase 3: normalize, compute bilinear, pre-fuse weights, byte offsets
    if (tid < NATT_) {
        const int hh = tid / (NL_*NP_);
        const int j  = tid - hh * (NL_*NP_);
        const int l = j / NP_;
        const int p = j - l * NP_;

        float sum = 0.f;
        #pragma unroll
        for (int jj = 0; jj < NL_*NP_; jj++) sum += s_e[hh][jj];
        const float ws = s_e[hh][j] / sum;

        const float* offp = &oa[hh * (NL_*NP_*2) + l * (NP_*2) + p * 2];
        float px = s_uv[0] * c_SX[l] + offp[0] - 0.5f;
        float py = s_uv[1] * c_SY[l] + offp[1] - 0.5f;
        float x0 = floorf(px), y0 = floorf(py);
        float fx = px - x0, fy = py - y0;
        const int wl = c_W[l], hl = c_H[l];
        const int base_l = b * TOTHW_ + c_OFF[l];

        int   idv[4];
        float bwv[4];
        #pragma unroll
        for (int c = 0; c < 4; c++) {
            int dx = c & 1, dy = c >> 1;
            float xi = x0 + dx, yi = y0 + dy;
            bool valid = (xi >= 0.f) && (xi < (float)wl) && (yi >= 0.f) && (yi < (float)hl);
            float wgt = (dx ? fx : 1.f - fx) * (dy ? fy : 1.f - fy);
            float xc = fminf(fmaxf(xi, 0.f), (float)(wl - 1));
            float yc = fminf(fmaxf(yi, 0.f), (float)(hl - 1));
            int pix = (int)yc * wl + (int)xc;
            idv[c] = ((base_l + pix) * NHD_ + hh * DH_) * 2;   // byte offset
            bwv[c] = valid ? (ws * wgt) : 0.f;                 // pre-fused weight
        }
        s_idx[hh][j] = make_int4(idv[0], idv[1], idv[2], idv[3]);
        s_wb[hh][j]  = make_float4(bwv[0], bwv[1], bwv[2], bwv[3]);
    }
    if (tid < NH_) {
        s_idx[tid][27] = make_int4(0, 0, 0, 0);
        s_wb[tid][27]  = make_float4(0.f, 0.f, 0.f, 0.f);
    }
    __syncthreads();

    // gather loop: pure weighted accumulation
    const char* vb = reinterpret_cast<const char*>(g_vh16) + l8 * 16;
    float a[8];
    #pragma unroll
    for (int k = 0; k < 8; k++) a[k] = 0.f;

    #pragma unroll
    for (int jp = 0; jp < 7; jp++) {
        const int j = jp * 4 + g;
        const int4   id = s_idx[h][j];
        const float4 wb = s_wb[h][j];
        const int ids[4] = {id.x, id.y, id.z, id.w};
        const float ws4[4] = {wb.x, wb.y, wb.z, wb.w};
        #pragma unroll
        for (int c = 0; c < 4; c++) {
            uint4 u = *reinterpret_cast<const uint4*>(vb + ids[c]);
            float w = ws4[c];
            float2 f0 = __half22float2(*reinterpret_cast<__half2*>(&u.x));
            float2 f1 = __half22float2(*reinterpret_cast<__half2*>(&u.y));
            float2 f2 = __half22float2(*reinterpret_cast<__half2*>(&u.z));
            float2 f3 = __half22float2(*reinterpret_cast<__half2*>(&u.w));
            a[0] += w * f0.x; a[1] += w * f0.y;
            a[2] += w * f1.x; a[3] += w * f1.y;
            a[4] += w * f2.x; a[5] += w * f2.y;
            a[6] += w * f3.x; a[7] += w * f3.y;
        }
    }

    #pragma unroll
    for (int k = 0; k < 8; k++) {
        a[k] += __shfl_xor_sync(0xffffffffu, a[k], 8);
        a[k] += __shfl_xor_sync(0xffffffffu, a[k], 16);
    }

    if (g == 0) {
        long oidx = bq * NHD_ + h * DH_ + l8 * 8;
        __half hv[8];
        #pragma unroll
        for (int k = 0; k < 8; k++) hv[k] = __float2half_rn(a[k]);
        *reinterpret_cast<uint4*>(&g_mid16[oidx]) = *reinterpret_cast<uint4*>(hv);
    }
}

// ---------------- host launcher ----------------
extern "C" void kernel_launch(void* const* d_in, const int* in_sizes, int n_in,
                              void* d_out, int out_size)
{
    const float* x         = (const float*)d_in[0];
    const float* pe        = (const float*)d_in[1];
    const float* coor      = (const float*)d_in[2];
    const float* cam2img   = (const float*)d_in[3];
    const float* lidar2cam = (const float*)d_in[4];
    const float* feat0     = (const float*)d_in[5];
    const float* feat1     = (const float*)d_in[6];
    const float* feat2     = (const float*)d_in[7];
    const float* W_value   = (const float*)d_in[8];
    const float* b_value   = (const float*)d_in[9];
    const float* W_off     = (const float*)d_in[10];
    const float* b_off     = (const float*)d_in[11];
    const float* W_attn    = (const float*)d_in[12];
    const float* b_attn    = (const float*)d_in[13];
    const float* W_out     = (const float*)d_in[14];
    const float* b_out     = (const float*)d_in[15];
    float* out = (float*)d_out;

    float *poa, *pboa;
    __half *pv16, *pq16, *pf16, *pmid16, *pwh;
    cudaGetSymbolAddress((void**)&pv16, g_vh16);
    cudaGetSymbolAddress((void**)&poa, g_oa);
    cudaGetSymbolAddress((void**)&pboa, g_boa);
    cudaGetSymbolAddress((void**)&pq16, g_q16);
    cudaGetSymbolAddress((void**)&pf16, g_f16);
    cudaGetSymbolAddress((void**)&pmid16, g_mid16);
    cudaGetSymbolAddress((void**)&pwh, g_wh);

    static bool attrSet = false;
    if (!attrSet) {
        cudaFuncSetAttribute(f16_gemm_dual, cudaFuncAttributeMaxDynamicSharedMemorySize, GEMM_SMEM);
        attrSet = true;
    }

    // 1: weight transposes + bias concat
    {
        dim3 grid(12, 12, 5);
        prep_weights_kernel<<<grid, 256>>>(W_value, W_off, W_attn, W_out, b_off, b_attn);
    }
    // 2: fused data prep (feature transpose + q = x + pe)
    {
        int nb = FEAT_BLOCKS + (ADD_N4 + 255) / 256;   // 9136
        prep_data_kernel<<<nb, 256>>>(x, pe, feat0, feat1, feat2);
    }
    // 3: fused value + offsets/attn GEMMs (one launch)
    {
        GDesc dv;  // value: [B*TOTHW, 384] = f16 @ Wv
        dv.A = pf16; dv.Bh = pwh + WV_OFF;
        dv.bias = b_value; dv.C = pv16;
        dv.M = B_ * TOTHW_; dv.N = NHD_; dv.K = DM_; dv.halfOut = 1;
        dv.nbx = NHD_ / BN;  // 6
        int nv = dv.nbx * ((dv.M + BM - 1) / BM);   // 948

        GDesc doa; // offsets+attn: [B*NQ, 486] = q16 @ Woa
        doa.A = pq16; doa.Bh = pwh + WOA_OFF;
        doa.bias = pboa; doa.C = poa;
        doa.M = B_ * NQ_; doa.N = NOA_; doa.K = DM_; doa.halfOut = 0;
        doa.nbx = (NOA_ + BN - 1) / BN;  // 8
        int noa = doa.nbx * (doa.M / BM);            // 1024

        f16_gemm_dual<<<nv + noa, 128, GEMM_SMEM>>>(dv, doa, nv);
    }
    // 4: sampler v6
    {
        dim3 grid(NQ_, B_);
        sample_kernel<<<grid, 192>>>(coor, cam2img, lidar2cam);
    }
    // 5: output GEMM
    {
        GDesc dn;
        dn.A = pmid16; dn.Bh = pwh + WOUT_OFF;
        dn.bias = b_out; dn.C = out;
        dn.M = B_ * NQ_; dn.N = DM_; dn.K = NHD_; dn.halfOut = 0;
        dn.nbx = DM_ / BN;  // 4
        int nb = dn.nbx * (dn.M / BM);  // 512
        f16_gemm_dual<<<nb, 128, GEMM_SMEM>>>(dn, dn, nb);
    }
}

// round 17
// speedup vs baseline: 1.2370x; 1.0099x over previous
#include <cuda_runtime.h>
#include <cuda_bf16.h>
#include <cuda_fp16.h>
#include <math.h>
#include <stdint.h>

// ---------------- problem constants ----------------
#define B_   2
#define NQ_  8192
#define DM_  256
#define NH_  6
#define DH_  64
#define NL_  3
#define NP_  9
#define NHD_ (NH_*DH_)            // 384
#define NOFF_ (NH_*NL_*NP_*2)     // 324
#define NATT_ (NH_*NL_*NP_)       // 162
#define NOA_  (NOFF_ + NATT_)     // 486
#define TOTHW_ 10080              // 7680+1920+480

// level tables
__device__ __constant__ int   c_W[3]   = {160, 80, 40};
__device__ __constant__ int   c_H[3]   = {48, 24, 12};
__device__ __constant__ int   c_OFF[3] = {0, 7680, 9600};
__device__ __constant__ float c_SX[3]  = {160.f/1280.f, 80.f/1280.f, 40.f/1280.f};
__device__ __constant__ float c_SY[3]  = {48.f/384.f, 24.f/384.f, 12.f/384.f};

// ---------------- scratch (no allocs allowed) ----------------
__device__ __half g_vh16[(size_t)B_ * TOTHW_ * NHD_];   // value projection (fp16)
__device__ float g_oa  [(size_t)B_ * NQ_ * NOA_];       // offsets(324) | attn(162)
__device__ float g_boa [NOA_];

// single fp16 A-planes
__device__ __half g_q16 [(size_t)B_ * NQ_ * DM_];
__device__ __half g_f16 [(size_t)B_ * TOTHW_ * DM_];
__device__ __half g_mid16[(size_t)B_ * NQ_ * NHD_];

// weights transposed [N][K] fp16: Wv(384x256) | Woa(486x256) | Wout(256x384)
#define WV_OFF   0
#define WOA_OFF  (384*256)
#define WOUT_OFF (WOA_OFF + NOA_*256)
#define WTOT_    (WOUT_OFF + 256*384)
__device__ __half g_wh[WTOT_];

// ---------------- packed f32x2 helpers (sm_103a FFMA2) ----------------
__device__ __forceinline__ uint64_t pack2(float lo, float hi) {
    uint64_t r;
    asm("mov.b64 %0, {%1, %2};" : "=l"(r) : "f"(lo), "f"(hi));
    return r;
}
__device__ __forceinline__ void fma2(uint64_t& d, uint64_t a, uint64_t b) {
    asm("fma.rn.f32x2 %0, %1, %2, %0;" : "+l"(d) : "l"(a), "l"(b));
}
__device__ __forceinline__ void unpack2(uint64_t v, float& lo, float& hi) {
    asm("mov.b64 {%0, %1}, %2;" : "=f"(lo), "=f"(hi) : "l"(v));
}

// ================= prep kernels =================
// weight transposes (fp16) + bias concat
__global__ __launch_bounds__(256)
void prep_weights_kernel(const float* __restrict__ Wv, const float* __restrict__ Woff,
                         const float* __restrict__ Wattn, const float* __restrict__ Wout,
                         const float* __restrict__ boff, const float* __restrict__ battn)
{
    const int z = blockIdx.z;
    if (z == 4) {
        if (blockIdx.y != 0 || blockIdx.x > 1) return;
        int i = blockIdx.x * 256 + threadIdx.x;
        if (i < NOFF_) g_boa[i] = boff[i];
        else if (i < NOA_) g_boa[i] = battn[i - NOFF_];
        return;
    }
    int R, C; const float* in; long base; int rowOff = 0;
    if (z == 0)      { in = Wv;    R = 256; C = 384; base = WV_OFF; }
    else if (z == 1) { in = Woff;  R = 256; C = 324; base = WOA_OFF; }
    else if (z == 2) { in = Wattn; R = 256; C = 162; base = WOA_OFF; rowOff = 324; }
    else             { in = Wout;  R = 384; C = 256; base = WOUT_OFF; }

    const int c0 = blockIdx.x * 32, r0 = blockIdx.y * 32;
    if (c0 >= C || r0 >= R) return;

    __shared__ float t[32][33];
    const int tx = threadIdx.x & 31, ty = threadIdx.x >> 5;
    #pragma unroll
    for (int i = 0; i < 32; i += 8) {
        int r = r0 + ty + i, c = c0 + tx;
        t[ty + i][tx] = (r < R && c < C) ? in[(long)r * C + c] : 0.f;
    }
    __syncthreads();
    #pragma unroll
    for (int i = 0; i < 32; i += 8) {
        int c = c0 + ty + i, r = r0 + tx;
        if (c < C && r < R)
            g_wh[base + (long)(rowOff + c) * R + r] = __float2half_rn(t[tx][ty + i]);
    }
}

// fused data prep: feature transpose (blocks [0,5040)) + q=x+pe (blocks [5040,9136))
#define FEAT_BLOCKS 5040
#define ADD_N4 (B_*NQ_*DM_/4)       // 1048576
__global__ __launch_bounds__(256)
void prep_data_kernel(const float* __restrict__ x, const float* __restrict__ pe,
                      const float* __restrict__ f0, const float* __restrict__ f1,
                      const float* __restrict__ f2)
{
    const int bx = blockIdx.x;
    if (bx < FEAT_BLOCKS) {
        __shared__ float t[32][33];
        const int b  = bx / 2520;
        int rem = bx - b * 2520;
        const int ry = rem / 315;
        int xt = rem - ry * 315;
        int l, c0;
        const float* in;
        int hwl;
        if (xt < 240)      { l = 0; c0 = xt * 32;         in = f0; hwl = 7680; }
        else if (xt < 300) { l = 1; c0 = (xt - 240) * 32; in = f1; hwl = 1920; }
        else               { l = 2; c0 = (xt - 300) * 32; in = f2; hwl = 480;  }
        in += (long)b * DM_ * hwl;
        const int r0 = ry * 32;
        const int tx = threadIdx.x & 31, ty = threadIdx.x >> 5;

        #pragma unroll
        for (int i = 0; i < 32; i += 8)
            t[ty + i][tx] = in[(long)(r0 + ty + i) * hwl + c0 + tx];
        __syncthreads();
        const long outBase = ((long)b * TOTHW_ + c_OFF[l] + c0) * DM_ + r0;
        #pragma unroll
        for (int i = 0; i < 32; i += 8) {
            long o = outBase + (long)(ty + i) * DM_ + tx;
            g_f16[o] = __float2half_rn(t[tx][ty + i]);
        }
    } else {
        int i = (bx - FEAT_BLOCKS) * 256 + threadIdx.x;
        if (i >= ADD_N4) return;
        float4 a = reinterpret_cast<const float4*>(x)[i];
        float4 b = reinterpret_cast<const float4*>(pe)[i];
        __half h[4];
        h[0] = __float2half_rn(a.x + b.x);
        h[1] = __float2half_rn(a.y + b.y);
        h[2] = __float2half_rn(a.z + b.z);
        h[3] = __float2half_rn(a.w + b.w);
        *reinterpret_cast<uint2*>(g_q16 + (size_t)i*4) = *reinterpret_cast<uint2*>(h);
    }
}

// ================= fp16 tensor-core GEMM (dual-descriptor, single B plane) =================
#define BM 128
#define BN 64
#define BK 32
#define A_TILE_B (BM*BK*2)                 // 8192
#define B_TILE_B (BN*BK*2)                 // 4096
#define STAGE_B  (A_TILE_B + B_TILE_B)     // 12288
#define NSTAGE 3
#define GEMM_SMEM (NSTAGE*STAGE_B)         // 36864

struct GDesc {
    const __half* A;
    const __half* Bh;
    const float*  bias;
    void*         C;
    int M, N, K, halfOut, nbx;
};

#define MMAF16(d, a, b0v, b1v) \
  asm volatile("mma.sync.aligned.m16n8k16.row.col.f32.f16.f16.f32 " \
    "{%0,%1,%2,%3},{%4,%5,%6,%7},{%8,%9},{%0,%1,%2,%3};" \
    : "+f"((d)[0]), "+f"((d)[1]), "+f"((d)[2]), "+f"((d)[3]) \
    : "r"((a)[0]), "r"((a)[1]), "r"((a)[2]), "r"((a)[3]), "r"(b0v), "r"(b1v))

__device__ __forceinline__ uint32_t swz(uint32_t off) {
    return off ^ ((off >> 3) & 0x30);
}
__device__ __forceinline__ void ldsm4(uint32_t (&r)[4], uint32_t addr) {
    asm volatile("ldmatrix.sync.aligned.m8n8.x4.shared.b16 {%0,%1,%2,%3}, [%4];"
        : "=r"(r[0]), "=r"(r[1]), "=r"(r[2]), "=r"(r[3]) : "r"(addr));
}
__device__ __forceinline__ void cp16(uint32_t dst, const void* src, bool pred) {
    int sz = pred ? 16 : 0;
    asm volatile("cp.async.cg.shared.global [%0], [%1], 16, %2;\n"
                 :: "r"(dst), "l"(src), "r"(sz));
}

__global__ __launch_bounds__(128, 4)
void f16_gemm_dual(GDesc d0, GDesc d1, int split)
{
    extern __shared__ uint8_t sm8[];
    uint32_t smb;
    asm("{ .reg .u64 t; cvta.to.shared.u64 t, %1; cvt.u32.u64 %0, t; }" : "=r"(smb) : "l"(sm8));

    const bool first = (int)blockIdx.x < split;
    const GDesc d = first ? d0 : d1;
    const int idx = first ? blockIdx.x : (blockIdx.x - split);
    const int m0 = (idx / d.nbx) * BM;
    const int n0 = (idx % d.nbx) * BN;
    const int M = d.M, N = d.N, K = d.K;

    const int tid = threadIdx.x;
    const int lane = tid & 31, wm = tid >> 5;
    const int r = lane >> 2, cc = lane & 3;

    float acc[2][8][4];
    #pragma unroll
    for (int i = 0; i < 2; i++)
        #pragma unroll
        for (int j = 0; j < 8; j++)
            #pragma unroll
            for (int t = 0; t < 4; t++) acc[i][j][t] = 0.f;

    const int nst = K / BK;

    auto LOAD = [&](int s, int buf) {
        uint32_t base = smb + buf * STAGE_B;
        const int k0 = s * BK;
        #pragma unroll
        for (int i = 0; i < 4; i++) {
            int c = tid + i * 128;
            int row = c >> 2, col = c & 3;
            bool p = (m0 + row) < M;
            long g = (long)(p ? (m0 + row) : 0) * K + k0 + col * 8;
            uint32_t so = swz((uint32_t)(row * 64 + col * 16));
            cp16(base + so, d.A + g, p);
        }
        #pragma unroll
        for (int i = 0; i < 2; i++) {
            int c = tid + i * 128;
            int row = c >> 2, col = c & 3;
            bool p = (n0 + row) < N;
            long g = (long)(p ? (n0 + row) : 0) * K + k0 + col * 8;
            uint32_t so = swz((uint32_t)(row * 64 + col * 16));
            cp16(base + A_TILE_B + so, d.Bh + g, p);
        }
        asm volatile("cp.async.commit_group;\n" ::: "memory");
    };

    auto COMPUTE = [&](int buf) {
        uint32_t base = smb + buf * STAGE_B;
        #pragma unroll
        for (int kk = 0; kk < 2; kk++) {
            const uint32_t koff = (uint32_t)((kk * 2 + (lane >> 4)) * 16);
            uint32_t a[2][4];
            #pragma unroll
            for (int mt = 0; mt < 2; mt++) {
                int row = wm * 32 + mt * 16 + (lane & 15);
                ldsm4(a[mt], base + swz((uint32_t)(row * 64) + koff));
            }
            uint32_t bh[2][4];
            {
                int row = (lane & 15);
                ldsm4(bh[0], base + A_TILE_B + swz((uint32_t)(row * 64) + koff));
            }
            #pragma unroll
            for (int nt2 = 0; nt2 < 4; nt2++) {
                const int cur = nt2 & 1, nxt = cur ^ 1;
                if (nt2 < 3) {
                    int row = (nt2 + 1) * 16 + (lane & 15);
                    ldsm4(bh[nxt], base + A_TILE_B + swz((uint32_t)(row * 64) + koff));
                }
                #pragma unroll
                for (int mt = 0; mt < 2; mt++)
                    #pragma unroll
                    for (int hv = 0; hv < 2; hv++) {
                        int nt = nt2 * 2 + hv;
                        MMAF16(acc[mt][nt], a[mt], bh[cur][hv], bh[cur][hv + 2]);
                    }
            }
        }
    };

    LOAD(0, 0);
    if (nst > 1) LOAD(1, 1);
    for (int s = 0; s < nst; s++) {
        if (s + 1 < nst) { asm volatile("cp.async.wait_group 1;\n" ::: "memory"); }
        else             { asm volatile("cp.async.wait_group 0;\n" ::: "memory"); }
        __syncthreads();
        if (s + 2 < nst) LOAD(s + 2, (s + 2) % NSTAGE);
        COMPUTE(s % NSTAGE);
    }

    if (d.halfOut) {
        __half* C = (__half*)d.C;
        #pragma unroll
        for (int mt = 0; mt < 2; mt++) {
            int m = m0 + wm * 32 + mt * 16 + r;
            #pragma unroll
            for (int nt = 0; nt < 8; nt++) {
                int n = n0 + nt * 8 + cc * 2;
                const float* dd = acc[mt][nt];
                if (n + 1 < N) {
                    float b0 = d.bias[n], b1 = d.bias[n + 1];
                    if (m < M)
                        *(__half2*)&C[(long)m * N + n] = __floats2half2_rn(dd[0] + b0, dd[1] + b1);
                    if (m + 8 < M)
                        *(__half2*)&C[(long)(m + 8) * N + n] = __floats2half2_rn(dd[2] + b0, dd[3] + b1);
                } else if (n < N) {
                    float b0 = d.bias[n];
                    if (m < M)     C[(long)m * N + n]       = __float2half_rn(dd[0] + b0);
                    if (m + 8 < M) C[(long)(m + 8) * N + n] = __float2half_rn(dd[2] + b0);
                }
            }
        }
    } else {
        float* C = (float*)d.C;
        #pragma unroll
        for (int mt = 0; mt < 2; mt++) {
            int m = m0 + wm * 32 + mt * 16 + r;
            #pragma unroll
            for (int nt = 0; nt < 8; nt++) {
                int n = n0 + nt * 8 + cc * 2;
                const float* dd = acc[mt][nt];
                if (m < M) {
                    if (n < N)     C[(long)m * N + n]     = dd[0] + d.bias[n];
                    if (n + 1 < N) C[(long)m * N + n + 1] = dd[1] + d.bias[n + 1];
                }
                if (m + 8 < M) {
                    if (n < N)     C[(long)(m + 8) * N + n]     = dd[2] + d.bias[n];
                    if (n + 1 < N) C[(long)(m + 8) * N + n + 1] = dd[3] + d.bias[n + 1];
                }
            }
        }
    }
}

// ---------------- sampler v7: v6 + packed FFMA2 accumulation ----------------
// Gather loop math per corner: 8x F2F (unpack) + 4x fma.rn.f32x2 (was 8x FFMA).
// Numerics identical to v6 (fma.rn.f32x2 == two fmaf).
__global__ __launch_bounds__(192)
void sample_kernel(const float* __restrict__ coor,
                   const float* __restrict__ cam2img,
                   const float* __restrict__ lidar2cam)
{
    const int q = blockIdx.x;
    const int b = blockIdx.y;
    const int tid = threadIdx.x;
    const int h    = tid >> 5;
    const int lane = tid & 31;
    const int g    = lane >> 3;
    const int l8   = lane & 7;

    __shared__ float  s_uv[2];
    __shared__ float  s_logit[NH_][NL_*NP_];
    __shared__ float  s_e[NH_][NL_*NP_];
    __shared__ int4   s_idx[NH_][28];     // byte offsets into g_vh16
    __shared__ float4 s_wb[NH_][28];      // softmax * bilinear, pre-fused

    // projection (one thread)
    if (tid == 0) {
        const float* L  = lidar2cam + b * 16;
        const float* Kc = cam2img + b * 16;
        float p0 = coor[((long)b * NQ_ + q) * 3 + 0];
        float p1 = coor[((long)b * NQ_ + q) * 3 + 1];
        float p2 = coor[((long)b * NQ_ + q) * 3 + 2];
        float pc[3], pr[3];
        #pragma unroll
        for (int i = 0; i < 3; i++)
            pc[i] = L[i*4+0]*p0 + L[i*4+1]*p1 + L[i*4+2]*p2 + L[i*4+3];
        #pragma unroll
        for (int i = 0; i < 3; i++)
            pr[i] = Kc[i*4+0]*pc[0] + Kc[i*4+1]*pc[1] + Kc[i*4+2]*pc[2] + Kc[i*4+3];
        s_uv[0] = pr[0] / pr[2];
        s_uv[1] = pr[1] / pr[2];
    }

    const long bq = (long)b * NQ_ + q;
    const float* oa = g_oa + bq * NOA_;

    // phase 1: logits -> smem
    if (tid < NATT_) {
        const int hh = tid / (NL_*NP_);
        const int j  = tid - hh * (NL_*NP_);
        s_logit[hh][j] = oa[NOFF_ + hh * (NL_*NP_) + j];
    }
    __syncthreads();

    // phase 2: exp(l - max)
    if (tid < NATT_) {
        const int hh = tid / (NL_*NP_);
        const int j  = tid - hh * (NL_*NP_);
        float mx = -1e30f;
        #pragma unroll
        for (int jj = 0; jj < NL_*NP_; jj++) mx = fmaxf(mx, s_logit[hh][jj]);
        s_e[hh][j] = expf(s_logit[hh][j] - mx);
    }
    __syncthreads();

    // phase 3: normalize, compute bilinear, pre-fuse weights, byte offsets
    if (tid < NATT_) {
        const int hh = tid / (NL_*NP_);
        const int j  = tid - hh * (NL_*NP_);
        const int l = j / NP_;
        const int p = j - l * NP_;

        float sum = 0.f;
        #pragma unroll
        for (int jj = 0; jj < NL_*NP_; jj++) sum += s_e[hh][jj];
        const float ws = s_e[hh][j] / sum;

        const float* offp = &oa[hh * (NL_*NP_*2) + l * (NP_*2) + p * 2];
        float px = s_uv[0] * c_SX[l] + offp[0] - 0.5f;
        float py = s_uv[1] * c_SY[l] + offp[1] - 0.5f;
        float x0 = floorf(px), y0 = floorf(py);
        float fx = px - x0, fy = py - y0;
        const int wl = c_W[l], hl = c_H[l];
        const int base_l = b * TOTHW_ + c_OFF[l];

        int   idv[4];
        float bwv[4];
        #pragma unroll
        for (int c = 0; c < 4; c++) {
            int dx = c & 1, dy = c >> 1;
            float xi = x0 + dx, yi = y0 + dy;
            bool valid = (xi >= 0.f) && (xi < (float)wl) && (yi >= 0.f) && (yi < (float)hl);
            float wgt = (dx ? fx : 1.f - fx) * (dy ? fy : 1.f - fy);
            float xc = fminf(fmaxf(xi, 0.f), (float)(wl - 1));
            float yc = fminf(fmaxf(yi, 0.f), (float)(hl - 1));
            int pix = (int)yc * wl + (int)xc;
            idv[c] = ((base_l + pix) * NHD_ + hh * DH_) * 2;   // byte offset
            bwv[c] = valid ? (ws * wgt) : 0.f;                 // pre-fused weight
        }
        s_idx[hh][j] = make_int4(idv[0], idv[1], idv[2], idv[3]);
        s_wb[hh][j]  = make_float4(bwv[0], bwv[1], bwv[2], bwv[3]);
    }
    if (tid < NH_) {
        s_idx[tid][27] = make_int4(0, 0, 0, 0);
        s_wb[tid][27]  = make_float4(0.f, 0.f, 0.f, 0.f);
    }
    __syncthreads();

    // gather loop: packed-pair weighted accumulation (FFMA2)
    const char* vb = reinterpret_cast<const char*>(g_vh16) + l8 * 16;
    uint64_t acc2[4];
    #pragma unroll
    for (int k = 0; k < 4; k++) acc2[k] = pack2(0.f, 0.f);

    #pragma unroll
    for (int jp = 0; jp < 7; jp++) {
        const int j = jp * 4 + g;
        const int4   id = s_idx[h][j];
        const float4 wb = s_wb[h][j];
        const int ids[4] = {id.x, id.y, id.z, id.w};
        const float ws4[4] = {wb.x, wb.y, wb.z, wb.w};
        #pragma unroll
        for (int c = 0; c < 4; c++) {
            uint4 u = *reinterpret_cast<const uint4*>(vb + ids[c]);
            uint64_t w2 = pack2(ws4[c], ws4[c]);
            float2 f0 = __half22float2(*reinterpret_cast<__half2*>(&u.x));
            float2 f1 = __half22float2(*reinterpret_cast<__half2*>(&u.y));
            float2 f2 = __half22float2(*reinterpret_cast<__half2*>(&u.z));
            float2 f3 = __half22float2(*reinterpret_cast<__half2*>(&u.w));
            fma2(acc2[0], pack2(f0.x, f0.y), w2);
            fma2(acc2[1], pack2(f1.x, f1.y), w2);
            fma2(acc2[2], pack2(f2.x, f2.y), w2);
            fma2(acc2[3], pack2(f3.x, f3.y), w2);
        }
    }

    float a[8];
    #pragma unroll
    for (int k = 0; k < 4; k++) unpack2(acc2[k], a[2*k], a[2*k + 1]);

    #pragma unroll
    for (int k = 0; k < 8; k++) {
        a[k] += __shfl_xor_sync(0xffffffffu, a[k], 8);
        a[k] += __shfl_xor_sync(0xffffffffu, a[k], 16);
    }

    if (g == 0) {
        long oidx = bq * NHD_ + h * DH_ + l8 * 8;
        __half hv[8];
        #pragma unroll
        for (int k = 0; k < 8; k++) hv[k] = __float2half_rn(a[k]);
        *reinterpret_cast<uint4*>(&g_mid16[oidx]) = *reinterpret_cast<uint4*>(hv);
    }
}

// ---------------- host launcher ----------------
extern "C" void kernel_launch(void* const* d_in, const int* in_sizes, int n_in,
                              void* d_out, int out_size)
{
    const float* x         = (const float*)d_in[0];
    const float* pe        = (const float*)d_in[1];
    const float* coor      = (const float*)d_in[2];
    const float* cam2img   = (const float*)d_in[3];
    const float* lidar2cam = (const float*)d_in[4];
    const float* feat0     = (const float*)d_in[5];
    const float* feat1     = (const float*)d_in[6];
    const float* feat2     = (const float*)d_in[7];
    const float* W_value   = (const float*)d_in[8];
    const float* b_value   = (const float*)d_in[9];
    const float* W_off     = (const float*)d_in[10];
    const float* b_off     = (const float*)d_in[11];
    const float* W_attn    = (const float*)d_in[12];
    const float* b_attn    = (const float*)d_in[13];
    const float* W_out     = (const float*)d_in[14];
    const float* b_out     = (const float*)d_in[15];
    float* out = (float*)d_out;

    float *poa, *pboa;
    __half *pv16, *pq16, *pf16, *pmid16, *pwh;
    cudaGetSymbolAddress((void**)&pv16, g_vh16);
    cudaGetSymbolAddress((void**)&poa, g_oa);
    cudaGetSymbolAddress((void**)&pboa, g_boa);
    cudaGetSymbolAddress((void**)&pq16, g_q16);
    cudaGetSymbolAddress((void**)&pf16, g_f16);
    cudaGetSymbolAddress((void**)&pmid16, g_mid16);
    cudaGetSymbolAddress((void**)&pwh, g_wh);

    static bool attrSet = false;
    if (!attrSet) {
        cudaFuncSetAttribute(f16_gemm_dual, cudaFuncAttributeMaxDynamicSharedMemorySize, GEMM_SMEM);
        attrSet = true;
    }

    // 1: weight transposes + bias concat
    {
        dim3 grid(12, 12, 5);
        prep_weights_kernel<<<grid, 256>>>(W_value, W_off, W_attn, W_out, b_off, b_attn);
    }
    // 2: fused data prep (feature transpose + q = x + pe)
    {
        int nb = FEAT_BLOCKS + (ADD_N4 + 255) / 256;   // 9136
        prep_data_kernel<<<nb, 256>>>(x, pe, feat0, feat1, feat2);
    }
    // 3: fused value + offsets/attn GEMMs (one launch)
    {
        GDesc dv;  // value: [B*TOTHW, 384] = f16 @ Wv
        dv.A = pf16; dv.Bh = pwh + WV_OFF;
        dv.bias = b_value; dv.C = pv16;
        dv.M = B_ * TOTHW_; dv.N = NHD_; dv.K = DM_; dv.halfOut = 1;
        dv.nbx = NHD_ / BN;  // 6
        int nv = dv.nbx * ((dv.M + BM - 1) / BM);   // 948

        GDesc doa; // offsets+attn: [B*NQ, 486] = q16 @ Woa
        doa.A = pq16; doa.Bh = pwh + WOA_OFF;
        doa.bias = pboa; doa.C = poa;
        doa.M = B_ * NQ_; doa.N = NOA_; doa.K = DM_; doa.halfOut = 0;
        doa.nbx = (NOA_ + BN - 1) / BN;  // 8
        int noa = doa.nbx * (doa.M / BM);            // 1024

        f16_gemm_dual<<<nv + noa, 128, GEMM_SMEM>>>(dv, doa, nv);
    }
    // 4: sampler v7
    {
        dim3 grid(NQ_, B_);
        sample_kernel<<<grid, 192>>>(coor, cam2img, lidar2cam);
    }
    // 5: output GEMM
    {
        GDesc dn;
        dn.A = pmid16; dn.Bh = pwh + WOUT_OFF;
        dn.bias = b_out; dn.C = out;
        dn.M = B_ * NQ_; dn.N = DM_; dn.K = NHD_; dn.halfOut = 0;
        dn.nbx = DM_ / BN;  // 4
        int nb = dn.nbx * (dn.M / BM);  // 512
        f16_gemm_dual<<<nb, 128, GEMM_SMEM>>>(dn, dn, nb);
    }
}